// round 14
// baseline (speedup 1.0000x reference)
#include <cuda_runtime.h>
#include <cstdint>
#include <math.h>

// Problem sizes (fixed)
#define BB   4
#define TT   1024
#define CC   512
#define HH   8
#define NN   64
#define BT   (BB*TT)
#define BTC  (BT*CC)
#define SPAD (10*CC)
#define BKPAD (16*HH)

typedef unsigned long long u64;

__device__ float g_gate[BT*HH];
__device__ float g_k[BTC], g_vraw[BTC];
__device__ float g_hw[BT*64], g_ha[BT*64], g_hv[BT*32], g_hg[BT*128];
__device__ float g_a[BTC], g_g[BTC];
__device__ float g_r[BTC+2*SPAD], g_dec[BTC+2*SPAD], g_v[BTC+2*SPAD];
__device__ float g_kp[BTC+2*SPAD], g_aa[BTC+2*SPAD], g_bb[BTC+2*SPAD];
__device__ float g_af[BTC+2*SPAD], g_ab[BTC+2*SPAD];
__device__ float2 g_bkf[BT*HH + 2*BKPAD], g_bkb[BT*HH + 2*BKPAD];
__device__ float g_yf[BTC+2*SPAD], g_yb[BTC+2*SPAD];
__device__ float g_z[BTC];

__device__ __forceinline__ u64 fma2(u64 a, u64 b, u64 c) {
    u64 d; asm("fma.rn.f32x2 %0, %1, %2, %3;" : "=l"(d) : "l"(a), "l"(b), "l"(c));
    return d;
}
__device__ __forceinline__ u64 mul2(u64 a, u64 b) {
    u64 d; asm("mul.rn.f32x2 %0, %1, %2;" : "=l"(d) : "l"(a), "l"(b));
    return d;
}
__device__ __forceinline__ u64 pack2(float x) {
    u64 d; uint32_t r = __float_as_uint(x);
    asm("mov.b64 %0, {%1, %1};" : "=l"(d) : "r"(r));
    return d;
}
__device__ __forceinline__ float sum2(u64 a) {
    uint32_t lo, hi;
    asm("mov.b64 {%0, %1}, %2;" : "=r"(lo), "=r"(hi) : "l"(a));
    return __uint_as_float(lo) + __uint_as_float(hi);
}

// ---------------------------------------------------------------------------
// gate kernel
// ---------------------------------------------------------------------------
__global__ void gate_kernel(const float* __restrict__ x,
                            const float* __restrict__ gate_w)
{
    int bt = blockIdx.x;
    int t  = bt & (TT - 1);
    int tid = threadIdx.x;
    int c  = tid * 4;
    size_t base = (size_t)bt * CC + c;

    float4 xc = *(const float4*)(x + base);
    float4 xp = make_float4(0.f, 0.f, 0.f, 0.f);
    if (t != 0) xp = *(const float4*)(x + base - CC);

    float4 gw = *(const float4*)(gate_w + c);
    float p = (xp.x - xc.x)*gw.x + (xp.y - xc.y)*gw.y
            + (xp.z - xc.z)*gw.z + (xp.w - xc.w)*gw.w;
    #pragma unroll
    for (int o = 1; o < 16; o <<= 1) p += __shfl_xor_sync(0xffffffffu, p, o);
    if ((tid & 15) == 0)
        g_gate[bt*HH + (tid >> 4)] = 1.f / (1.f + expf(-p));
}

__device__ __forceinline__ float4 load_mixed(const float* __restrict__ A,
                                             const float* __restrict__ mix,
                                             int row, int kc, int K)
{
    const float* ap = A + (size_t)row * K + kc;
    float4 xc = *(const float4*)ap;
    if (mix == nullptr) return xc;
    float4 xp = make_float4(0.f, 0.f, 0.f, 0.f);
    if (row & (TT - 1)) xp = *(const float4*)(ap - CC);
    float4 mx = *(const float4*)(mix + kc);
    float4 o;
    o.x = xc.x + (xp.x - xc.x) * mx.x;
    o.y = xc.y + (xp.y - xc.y) * mx.y;
    o.z = xc.z + (xp.z - xc.z) * mx.z;
    o.w = xc.w + (xp.w - xc.w) * mx.w;
    return o;
}

__device__ __forceinline__ uint32_t f2tf32(float x) {
    uint32_t r;
    asm("cvt.rna.tf32.f32 %0, %1;" : "=r"(r) : "f"(x));
    return r;
}

__device__ __forceinline__ void mma_tf32(float* d, const uint32_t* a, const uint32_t* b) {
    asm("mma.sync.aligned.m16n8k8.row.col.f32.tf32.tf32.f32 "
        "{%0,%1,%2,%3},{%4,%5,%6,%7},{%8,%9},{%0,%1,%2,%3};"
        : "+f"(d[0]), "+f"(d[1]), "+f"(d[2]), "+f"(d[3])
        : "r"(a[0]), "r"(a[1]), "r"(a[2]), "r"(a[3]), "r"(b[0]), "r"(b[1]));
}

// ---------------------------------------------------------------------------
// tf32 GEMM (B transposed, [N,K]): QKV + Wo
// ---------------------------------------------------------------------------
struct QkvJobs {
    const float* A[3];
    const float* W[3];
    float*       C[3];
    const float* mix[3];
};

__global__ __launch_bounds__(256, 2) void gemm_tf32_nt(QkvJobs J)
{
    const int K = 512, N = 512;
    const float* A = J.A[blockIdx.z];
    const float* W = J.W[blockIdx.z];
    float*       C = J.C[blockIdx.z];
    const float* mix = J.mix[blockIdx.z];

    int m0 = blockIdx.y * 128;
    int n0 = blockIdx.x * 64;

    __shared__ uint32_t As[32][136];
    __shared__ uint32_t Bs[32][72];

    int tid  = threadIdx.x;
    int warp = tid >> 5, lane = tid & 31;
    int g = lane >> 2, c = lane & 3;
    int wm = warp & 3, wn = warp >> 2;

    float acc[2][4][4];
    #pragma unroll
    for (int mt = 0; mt < 2; mt++)
        #pragma unroll
        for (int nt = 0; nt < 4; nt++)
            #pragma unroll
            for (int r = 0; r < 4; r++) acc[mt][nt][r] = 0.f;

    for (int k0 = 0; k0 < K; k0 += 32) {
        #pragma unroll
        for (int it = 0; it < 4; it++) {
            int idx = tid + it * 256;
            int m = idx >> 3, kc = (idx & 7) * 4;
            float4 v = load_mixed(A, mix, m0 + m, k0 + kc, K);
            As[kc+0][m] = f2tf32(v.x);
            As[kc+1][m] = f2tf32(v.y);
            As[kc+2][m] = f2tf32(v.z);
            As[kc+3][m] = f2tf32(v.w);
        }
        #pragma unroll
        for (int it = 0; it < 2; it++) {
            int idx = tid + it * 256;
            int n = idx >> 3, kc = (idx & 7) * 4;
            float4 v = *(const float4*)(W + (size_t)(n0 + n) * K + k0 + kc);
            Bs[kc+0][n] = f2tf32(v.x);
            Bs[kc+1][n] = f2tf32(v.y);
            Bs[kc+2][n] = f2tf32(v.z);
            Bs[kc+3][n] = f2tf32(v.w);
        }
        __syncthreads();

        #pragma unroll
        for (int k8 = 0; k8 < 4; k8++) {
            int kr = k8 * 8;
            uint32_t a[2][4], b[4][2];
            #pragma unroll
            for (int mt = 0; mt < 2; mt++) {
                int mb = wm * 32 + mt * 16;
                a[mt][0] = As[kr + c    ][mb + g    ];
                a[mt][1] = As[kr + c    ][mb + g + 8];
                a[mt][2] = As[kr + c + 4][mb + g    ];
                a[mt][3] = As[kr + c + 4][mb + g + 8];
            }
            #pragma unroll
            for (int nt = 0; nt < 4; nt++) {
                int nb = wn * 32 + nt * 8;
                b[nt][0] = Bs[kr + c    ][nb + g];
                b[nt][1] = Bs[kr + c + 4][nb + g];
            }
            #pragma unroll
            for (int mt = 0; mt < 2; mt++)
                #pragma unroll
                for (int nt = 0; nt < 4; nt++)
                    mma_tf32(acc[mt][nt], a[mt], b[nt]);
        }
        __syncthreads();
    }

    #pragma unroll
    for (int mt = 0; mt < 2; mt++) {
        int row = m0 + wm * 32 + mt * 16 + g;
        #pragma unroll
        for (int nt = 0; nt < 4; nt++) {
            int col = n0 + wn * 32 + nt * 8 + 2 * c;
            float2 v0 = make_float2(acc[mt][nt][0], acc[mt][nt][1]);
            float2 v1 = make_float2(acc[mt][nt][2], acc[mt][nt][3]);
            *(float2*)(C + (size_t)row * N + col)       = v0;
            *(float2*)(C + (size_t)(row + 8) * N + col) = v1;
        }
    }
}

// ---------------------------------------------------------------------------
// tf32 multi-job GEMM, B in [K,N] layout, fused epilogues (0 none, 2 sigmoid,
// 4 vmix) + fused mixing. For stage-1 {a, v-hidden, g-hidden} and
// stage-2 {a, v, g}. K, N multiples of 32.
// ---------------------------------------------------------------------------
struct Tf32Jobs {
    int count;
    int tileStart[4];
    const float* A[3];
    const float* Bm[3];   // [K, N]
    float*       Cm[3];
    int N[3];
    int K[3];
    int act[3];
    const float* bias[3];
    const float* aux1[3];
    const float* aux2[3];
    const float* mix[3];
};

__global__ __launch_bounds__(256, 2) void gemm_tf32_multi(Tf32Jobs J)
{
    int bx = blockIdx.x;
    int j = 0;
    while (bx >= J.tileStart[j + 1]) ++j;
    int n0 = (bx - J.tileStart[j]) * 64;
    int m0 = blockIdx.y * 128;

    const float* A = J.A[j];
    const float* B = J.Bm[j];
    float*       C = J.Cm[j];
    const int N = J.N[j];
    const int K = J.K[j];
    const float* mix = J.mix[j];

    __shared__ uint32_t As[32][136];
    __shared__ uint32_t Bs[32][72];

    int tid  = threadIdx.x;
    int warp = tid >> 5, lane = tid & 31;
    int g = lane >> 2, c = lane & 3;
    int wm = warp & 3, wn = warp >> 2;

    float acc[2][4][4];
    #pragma unroll
    for (int mt = 0; mt < 2; mt++)
        #pragma unroll
        for (int nt = 0; nt < 4; nt++)
            #pragma unroll
            for (int r = 0; r < 4; r++) acc[mt][nt][r] = 0.f;

    for (int k0 = 0; k0 < K; k0 += 32) {
        #pragma unroll
        for (int it = 0; it < 4; it++) {
            int idx = tid + it * 256;
            int m = idx >> 3, kc = (idx & 7) * 4;
            float4 v = load_mixed(A, mix, m0 + m, k0 + kc, K);
            As[kc+0][m] = f2tf32(v.x);
            As[kc+1][m] = f2tf32(v.y);
            As[kc+2][m] = f2tf32(v.z);
            As[kc+3][m] = f2tf32(v.w);
        }
        // B tile from [K,N]: rows k0..k0+31, cols n0..n0+63
        #pragma unroll
        for (int it = 0; it < 2; it++) {
            int idx = tid + it * 256;
            int kr = idx >> 4;
            int c4 = (idx & 15) * 4;
            float4 v = make_float4(0.f, 0.f, 0.f, 0.f);
            if (n0 + c4 < N)
                v = *(const float4*)(B + (size_t)(k0 + kr) * N + n0 + c4);
            Bs[kr][c4+0] = f2tf32(v.x);
            Bs[kr][c4+1] = f2tf32(v.y);
            Bs[kr][c4+2] = f2tf32(v.z);
            Bs[kr][c4+3] = f2tf32(v.w);
        }
        __syncthreads();

        #pragma unroll
        for (int k8 = 0; k8 < 4; k8++) {
            int kr = k8 * 8;
            uint32_t a[2][4], b[4][2];
            #pragma unroll
            for (int mt = 0; mt < 2; mt++) {
                int mb = wm * 32 + mt * 16;
                a[mt][0] = As[kr + c    ][mb + g    ];
                a[mt][1] = As[kr + c    ][mb + g + 8];
                a[mt][2] = As[kr + c + 4][mb + g    ];
                a[mt][3] = As[kr + c + 4][mb + g + 8];
            }
            #pragma unroll
            for (int nt = 0; nt < 4; nt++) {
                int nb = wn * 32 + nt * 8;
                b[nt][0] = Bs[kr + c    ][nb + g];
                b[nt][1] = Bs[kr + c + 4][nb + g];
            }
            #pragma unroll
            for (int mt = 0; mt < 2; mt++)
                #pragma unroll
                for (int nt = 0; nt < 4; nt++)
                    mma_tf32(acc[mt][nt], a[mt], b[nt]);
        }
        __syncthreads();
    }

    const int act = J.act[j];
    const float* bias = J.bias[j];
    const float* aux1 = J.aux1[j];
    const float* aux2 = J.aux2[j];

    #pragma unroll
    for (int mt = 0; mt < 2; mt++) {
        int row = m0 + wm * 32 + mt * 16 + g;
        #pragma unroll
        for (int nt = 0; nt < 4; nt++) {
            int col = n0 + wn * 32 + nt * 8 + 2 * c;
            #pragma unroll
            for (int rr = 0; rr < 2; rr++) {
                int r2 = row + rr * 8;
                #pragma unroll
                for (int cc = 0; cc < 2; cc++) {
                    int c2 = col + cc;
                    if (c2 < N) {
                        size_t idx = (size_t)r2 * N + c2;
                        float v = acc[mt][nt][rr*2+cc];
                        float o;
                        if (act == 0) {
                            o = v;
                        } else if (act == 2) {
                            float z = v + (bias ? bias[c2] : 0.f);
                            o = 1.f / (1.f + expf(-z));
                        } else {
                            float z = v + bias[c2];
                            float s = 1.f / (1.f + expf(-z));
                            float vr = aux1[idx];
                            o = vr + (aux2[idx] - vr) * s;
                        }
                        C[idx] = o;
                    }
                }
            }
        }
    }
}

// ---------------------------------------------------------------------------
// FFMA SGEMM — only the precision-critical w-chain jobs now.
// ---------------------------------------------------------------------------
#define GBM 128
#define GBN 64
#define GBK 16

struct GemmJobs {
    int count;
    int tileStart[5];
    const float* A[4];
    const float* Bm[4];
    float*       Cm[4];
    int N[4];
    int K[4];
    int transb[4];
    int act[4];
    const float* bias[4];
    const float* aux1[4];
    const float* aux2[4];
    const float* mix[4];
};

__global__ __launch_bounds__(256, 2) void gemm_multi(GemmJobs J)
{
    __shared__ __align__(16) float As[GBK][GBM + 4];
    __shared__ __align__(16) float Bs[GBK][GBN + 4];

    int bx = blockIdx.x;
    int j = 0;
    while (bx >= J.tileStart[j + 1]) ++j;
    int n0 = (bx - J.tileStart[j]) * GBN;
    int m0 = blockIdx.y * GBM;

    const float* A = J.A[j];
    const float* B = J.Bm[j];
    float*       C = J.Cm[j];
    const int N = J.N[j];
    const int K = J.K[j];
    const int tb = J.transb[j];
    const float* mix = J.mix[j];

    int tid = threadIdx.x;
    int tx = tid & 15, ty = tid >> 4;

    float acc[8][4];
    #pragma unroll
    for (int im = 0; im < 8; im++)
        #pragma unroll
        for (int in = 0; in < 4; in++) acc[im][in] = 0.f;

    for (int k0 = 0; k0 < K; k0 += GBK) {
        #pragma unroll
        for (int it = 0; it < 2; it++) {
            int lid = tid + it * 256;
            int row = lid >> 2, kc = lid & 3;
            float4 v = load_mixed(A, mix, m0 + row, k0 + kc * 4, K);
            As[kc*4+0][row] = v.x;
            As[kc*4+1][row] = v.y;
            As[kc*4+2][row] = v.z;
            As[kc*4+3][row] = v.w;
        }
        if (tb) {
            int row = tid >> 2, kc = tid & 3;
            float4 v = *(const float4*)(B + (size_t)(n0 + row) * K + k0 + kc * 4);
            Bs[kc*4+0][row] = v.x;
            Bs[kc*4+1][row] = v.y;
            Bs[kc*4+2][row] = v.z;
            Bs[kc*4+3][row] = v.w;
        } else {
            int kr = tid >> 4, c4 = (tid & 15) * 4;
            float4 v = make_float4(0.f, 0.f, 0.f, 0.f);
            if (n0 + c4 < N)
                v = *(const float4*)(B + (size_t)(k0 + kr) * N + n0 + c4);
            *(float4*)&Bs[kr][c4] = v;
        }
        __syncthreads();

        #pragma unroll
        for (int kk = 0; kk < GBK; kk++) {
            float4 bf = *(const float4*)&Bs[kk][tx * 4];
            float4 a0 = *(const float4*)&As[kk][ty * 8];
            float4 a1 = *(const float4*)&As[kk][ty * 8 + 4];
            float af[8] = {a0.x, a0.y, a0.z, a0.w, a1.x, a1.y, a1.z, a1.w};
            float bb2[4] = {bf.x, bf.y, bf.z, bf.w};
            #pragma unroll
            for (int im = 0; im < 8; im++)
                #pragma unroll
                for (int in = 0; in < 4; in++) acc[im][in] += af[im] * bb2[in];
        }
        __syncthreads();
    }

    const int act = J.act[j];
    const float* bias = J.bias[j];

    #pragma unroll
    for (int im = 0; im < 8; im++) {
        int row = m0 + ty * 8 + im;
        #pragma unroll
        for (int in = 0; in < 4; in++) {
            int col = n0 + tx * 4 + in;
            if (col < N) {
                size_t idx = (size_t)row * N + col;
                float v = acc[im][in];
                float o;
                if (act == 0) {
                    o = v;
                } else if (act == 1) {
                    o = tanhf(v);
                } else {
                    float z = v + bias[col];
                    float s = 1.f / (1.f + expf(-z));
                    o = expf(-0.60653065971263342f * s);
                }
                C[idx] = o;
            }
        }
    }
}

// ---------------------------------------------------------------------------
// post / prep2 / scan / combine (unchanged from R13)
// ---------------------------------------------------------------------------
__global__ void post_kernel(const float* __restrict__ k_k, const float* __restrict__ k_a)
{
    int bt = blockIdx.x;
    int tid = threadIdx.x;
    int c = tid * 4;
    size_t base = (size_t)bt * CC + c;

    float4 kv = *(const float4*)(g_k + base);
    float4 av = *(const float4*)(g_a + base);
    float4 kkc = *(const float4*)(k_k + c);
    float4 kac = *(const float4*)(k_a + c);

    float4 kk;
    kk.x = kv.x * kkc.x; kk.y = kv.y * kkc.y; kk.z = kv.z * kkc.z; kk.w = kv.w * kkc.w;
    float ss = kk.x*kk.x + kk.y*kk.y + kk.z*kk.z + kk.w*kk.w;
    #pragma unroll
    for (int o = 1; o < 16; o <<= 1) ss += __shfl_xor_sync(0xffffffffu, ss, o);

    float nrm = sqrtf(ss);
    float inv = 1.f / fmaxf(nrm, 1e-12f);

    float4 aa, bb, kp;
    aa.x = -kk.x * inv; aa.y = -kk.y * inv; aa.z = -kk.z * inv; aa.w = -kk.w * inv;
    bb.x = kk.x * inv * av.x; bb.y = kk.y * inv * av.y;
    bb.z = kk.z * inv * av.z; bb.w = kk.w * inv * av.w;
    kp.x = kv.x * (1.f + (av.x - 1.f) * kac.x);
    kp.y = kv.y * (1.f + (av.y - 1.f) * kac.y);
    kp.z = kv.z * (1.f + (av.z - 1.f) * kac.z);
    kp.w = kv.w * (1.f + (av.w - 1.f) * kac.w);

    *(float4*)(g_aa + SPAD + base) = aa;
    *(float4*)(g_bb + SPAD + base) = bb;
    *(float4*)(g_kp + SPAD + base) = kp;
}

__global__ void prep2_kernel()
{
    int bt = blockIdx.x;
    int t  = bt & (TT - 1);
    int tid = threadIdx.x;
    int c = tid * 4;
    int h = tid >> 4;
    size_t base = SPAD + (size_t)bt * CC + c;

    float4 av = *(const float4*)(g_aa + base);
    float4 z4 = make_float4(0.f, 0.f, 0.f, 0.f);
    float4 dp = z4, bp = z4, kpv = z4, dn = z4, bn = z4, kn = z4;
    if (t != 0) {
        dp  = *(const float4*)(g_dec + base - CC);
        bp  = *(const float4*)(g_bb  + base - CC);
        kpv = *(const float4*)(g_kp  + base - CC);
    }
    if (t != TT - 1) {
        dn = *(const float4*)(g_dec + base + CC);
        bn = *(const float4*)(g_bb  + base + CC);
        kn = *(const float4*)(g_kp  + base + CC);
    }

    float4 af, ab;
    af.x = dp.x*av.x; af.y = dp.y*av.y; af.z = dp.z*av.z; af.w = dp.w*av.w;
    ab.x = dn.x*av.x; ab.y = dn.y*av.y; ab.z = dn.z*av.z; ab.w = dn.w*av.w;
    *(float4*)(g_af + base) = af;
    *(float4*)(g_ab + base) = ab;

    float bf_ = bp.x*av.x + bp.y*av.y + bp.z*av.z + bp.w*av.w;
    float kf_ = kpv.x*av.x + kpv.y*av.y + kpv.z*av.z + kpv.w*av.w;
    float bb_ = bn.x*av.x + bn.y*av.y + bn.z*av.z + bn.w*av.w;
    float kb_ = kn.x*av.x + kn.y*av.y + kn.z*av.z + kn.w*av.w;
    #pragma unroll
    for (int o = 1; o < 16; o <<= 1) {
        bf_ += __shfl_xor_sync(0xffffffffu, bf_, o);
        kf_ += __shfl_xor_sync(0xffffffffu, kf_, o);
        bb_ += __shfl_xor_sync(0xffffffffu, bb_, o);
        kb_ += __shfl_xor_sync(0xffffffffu, kb_, o);
    }
    if ((tid & 15) == 0) {
        g_bkf[BKPAD + bt*HH + h] = make_float2(bf_, kf_);
        g_bkb[BKPAD + bt*HH + h] = make_float2(bb_, kb_);
    }
}

template<int CS>
__device__ __forceinline__ void scan_step(
    int tstep,
    u64& S0a, u64& S1a, u64& S0b, u64& S1b,
    u64 (&R)[4][2], u64 (&D)[4][2], u64 (&K)[4][2],
    u64 (&B)[4][2], u64 (&A2)[4][2],
    float (&V0)[4], float (&V1)[4], float2 (&BK)[4],
    float (&zf0)[2], float (&zf1)[2], float (&yf0)[2], float (&yf1)[2],
    float& sa_prev0, float& sa_prev1, float& vprev0, float& vprev1,
    const float*& pr4, const float*& pd4, const float*& pk4,
    const float*& pb4, const float*& pA6,
    const float*& pv04, const float*& pv14, const float2*& pbk4,
    float* py0, float* py1, int stride, int sbk, int q)
{
    constexpr int P = CS & 1;

    float2 bk = BK[CS];
    float sa0 = fmaf(vprev0, bk.y, fmaf(sa_prev0, bk.x, zf0[P]));
    float sa1 = fmaf(vprev1, bk.y, fmaf(sa_prev1, bk.x, zf1[P]));

    if (q == 0 && (unsigned)(tstep - 2) < (unsigned)TT) {
        *py0 = yf0[P]; *py1 = yf1[P];
    }

    u64 sa20 = pack2(sa0), sa21 = pack2(sa1);
    float v0s = V0[CS], v1s = V1[CS];
    u64 v20 = pack2(v0s), v21 = pack2(v1s);
    S0a = fma2(S0a, D[CS][0], fma2(sa20, B[CS][0], mul2(v20, K[CS][0])));
    S1a = fma2(S1a, D[CS][1], fma2(sa20, B[CS][1], mul2(v20, K[CS][1])));
    S0b = fma2(S0b, D[CS][0], fma2(sa21, B[CS][0], mul2(v21, K[CS][0])));
    S1b = fma2(S1b, D[CS][1], fma2(sa21, B[CS][1], mul2(v21, K[CS][1])));

    float ya = sum2(fma2(S1a, R[CS][1],  mul2(S0a, R[CS][0])));
    float za = sum2(fma2(S1a, A2[CS][1], mul2(S0a, A2[CS][0])));
    float yb = sum2(fma2(S1b, R[CS][1],  mul2(S0b, R[CS][0])));
    float zb = sum2(fma2(S1b, A2[CS][1], mul2(S0b, A2[CS][0])));

    sa_prev0 = sa0; sa_prev1 = sa1; vprev0 = v0s; vprev1 = v1s;

    {
        ulonglong2 rv = *(const ulonglong2*)pr4;
        ulonglong2 dv = *(const ulonglong2*)pd4;
        ulonglong2 kv = *(const ulonglong2*)pk4;
        ulonglong2 bv = *(const ulonglong2*)pb4;
        ulonglong2 av = *(const ulonglong2*)pA6;
        R[CS][0]  = rv.x; R[CS][1]  = rv.y;
        D[CS][0]  = dv.x; D[CS][1]  = dv.y;
        K[CS][0]  = kv.x; K[CS][1]  = kv.y;
        B[CS][0]  = bv.x; B[CS][1]  = bv.y;
        A2[CS][0] = av.x; A2[CS][1] = av.y;
        V0[CS] = *pv04;
        V1[CS] = *pv14;
        BK[CS] = *pbk4;
    }
    pr4 += stride; pd4 += stride; pk4 += stride; pb4 += stride;
    pA6 += stride; pv04 += stride; pv14 += stride; pbk4 += sbk;

    #pragma unroll
    for (int o = 1; o < 16; o <<= 1) {
        ya += __shfl_xor_sync(0xffffffffu, ya, o);
        za += __shfl_xor_sync(0xffffffffu, za, o);
        yb += __shfl_xor_sync(0xffffffffu, yb, o);
        zb += __shfl_xor_sync(0xffffffffu, zb, o);
    }
    yf0[P] = ya; zf0[P] = za; yf1[P] = yb; zf1[P] = zb;
}

__global__ __launch_bounds__(128, 2) void scan_kernel()
{
    int bx = blockIdx.x;
    int dir = bx >> 7;
    int b   = (bx >> 5) & 3;
    int h   = (bx >> 2) & 7;
    int rg  = bx & 3;
    int tid = threadIdx.x;
    int rp  = tid >> 4;
    int q   = tid & 15;
    int c0  = q * 4;
    int i0  = rg * 16 + rp;
    int i1  = i0 + 8;

    int t0 = dir ? (TT - 1) : 0;
    int stride = dir ? -CC : CC;
    int sbk = dir ? -HH : HH;
    size_t off = SPAD + (size_t)(b * TT + t0) * CC + h * NN;

    const float* pr = g_r   + off + c0;
    const float* pd = g_dec + off + c0;
    const float* pk = g_kp  + off + c0;
    const float* pb = g_bb  + off + c0;
    const float* pA = (dir ? g_ab : g_af) + off + c0;
    const float* pv0 = g_v + off + i0;
    const float* pv1 = g_v + off + i1;
    const float2* pbk = (dir ? g_bkb : g_bkf) + BKPAD + (size_t)(b * TT + t0) * HH + h;

    float* ybase = (dir ? g_yb : g_yf);
    float* py0 = ybase + off + i0 - 2*stride;
    float* py1 = ybase + off + i1 - 2*stride;

    u64 S0a = 0, S1a = 0, S0b = 0, S1b = 0;
    u64 R[4][2], D[4][2], K[4][2], B[4][2], A2[4][2];
    float V0[4], V1[4];
    float2 BK[4];

    #pragma unroll
    for (int s = 0; s < 4; s++) {
        ulonglong2 v;
        v = *(const ulonglong2*)(pr + s*stride);     R[s][0]=v.x;  R[s][1]=v.y;
        v = *(const ulonglong2*)(pd + s*stride);     D[s][0]=v.x;  D[s][1]=v.y;
        v = *(const ulonglong2*)(pk + s*stride);     K[s][0]=v.x;  K[s][1]=v.y;
        v = *(const ulonglong2*)(pb + s*stride);     B[s][0]=v.x;  B[s][1]=v.y;
        v = *(const ulonglong2*)(pA + (s+2)*stride); A2[s][0]=v.x; A2[s][1]=v.y;
        V0[s] = *(pv0 + s*stride);
        V1[s] = *(pv1 + s*stride);
        BK[s] = *(pbk + s*sbk);
    }

    const float* pr4  = pr + 4*stride;
    const float* pd4  = pd + 4*stride;
    const float* pk4  = pk + 4*stride;
    const float* pb4  = pb + 4*stride;
    const float* pA6  = pA + 6*stride;
    const float* pv04 = pv0 + 4*stride;
    const float* pv14 = pv1 + 4*stride;
    const float2* pbk4 = pbk + 4*sbk;

    float zf0[2] = {0.f, 0.f}, zf1[2] = {0.f, 0.f};
    float yf0[2] = {0.f, 0.f}, yf1[2] = {0.f, 0.f};
    float sa_prev0 = 0.f, sa_prev1 = 0.f, vprev0 = 0.f, vprev1 = 0.f;

    for (int t = 0; t < TT + 4; t += 4) {
        scan_step<0>(t+0, S0a,S1a,S0b,S1b, R,D,K,B,A2, V0,V1,BK, zf0,zf1,yf0,yf1,
                     sa_prev0,sa_prev1,vprev0,vprev1,
                     pr4,pd4,pk4,pb4,pA6,pv04,pv14,pbk4, py0,py1, stride,sbk,q);
        py0 += stride; py1 += stride;
        scan_step<1>(t+1, S0a,S1a,S0b,S1b, R,D,K,B,A2, V0,V1,BK, zf0,zf1,yf0,yf1,
                     sa_prev0,sa_prev1,vprev0,vprev1,
                     pr4,pd4,pk4,pb4,pA6,pv04,pv14,pbk4, py0,py1, stride,sbk,q);
        py0 += stride; py1 += stride;
        scan_step<2>(t+2, S0a,S1a,S0b,S1b, R,D,K,B,A2, V0,V1,BK, zf0,zf1,yf0,yf1,
                     sa_prev0,sa_prev1,vprev0,vprev1,
                     pr4,pd4,pk4,pb4,pA6,pv04,pv14,pbk4, py0,py1, stride,sbk,q);
        py0 += stride; py1 += stride;
        scan_step<3>(t+3, S0a,S1a,S0b,S1b, R,D,K,B,A2, V0,V1,BK, zf0,zf1,yf0,yf1,
                     sa_prev0,sa_prev1,vprev0,vprev1,
                     pr4,pd4,pk4,pb4,pA6,pv04,pv14,pbk4, py0,py1, stride,sbk,q);
        py0 += stride; py1 += stride;
    }
}

__global__ void combine_kernel(const float* __restrict__ r_k,
                               const float* __restrict__ ln_g,
                               const float* __restrict__ ln_b)
{
    int bt = blockIdx.x;
    int tid = threadIdx.x;
    int c = tid * 4;
    int h = tid >> 4;
    size_t base = (size_t)bt * CC + c;

    float4 yf = *(const float4*)(g_yf + SPAD + base);
    float4 yb = *(const float4*)(g_yb + SPAD + base);
    float gate = g_gate[bt * HH + h];

    float4 xo;
    xo.x = gate * yf.x + (1.f - gate) * yb.x;
    xo.y = gate * yf.y + (1.f - gate) * yb.y;
    xo.z = gate * yf.z + (1.f - gate) * yb.z;
    xo.w = gate * yf.w + (1.f - gate) * yb.w;

    float4 rv = *(const float4*)(g_r + SPAD + base);
    float4 kp = *(const float4*)(g_kp + SPAD + base);
    float4 vv = *(const float4*)(g_v + SPAD + base);
    float4 gv = *(const float4*)(g_g + base);
    float4 rk = *(const float4*)(r_k + c);

    float sum = xo.x + xo.y + xo.z + xo.w;
    float sq  = xo.x*xo.x + xo.y*xo.y + xo.z*xo.z + xo.w*xo.w;
    float sres = rv.x*kp.x*rk.x + rv.y*kp.y*rk.y + rv.z*kp.z*rk.z + rv.w*kp.w*rk.w;
    #pragma unroll
    for (int o = 1; o < 16; o <<= 1) {
        sum  += __shfl_xor_sync(0xffffffffu, sum, o);
        sq   += __shfl_xor_sync(0xffffffffu, sq, o);
        sres += __shfl_xor_sync(0xffffffffu, sres, o);
    }
    float mu = sum * (1.f / 64.f);
    float var = sq * (1.f / 64.f) - mu * mu;
    float rstd = rsqrtf(var + 0.00064f);

    float4 lg = *(const float4*)(ln_g + c);
    float4 lb = *(const float4*)(ln_b + c);

    float4 z;
    z.x = ((xo.x - mu) * rstd * lg.x + lb.x + sres * vv.x) * gv.x;
    z.y = ((xo.y - mu) * rstd * lg.y + lb.y + sres * vv.y) * gv.y;
    z.z = ((xo.z - mu) * rstd * lg.z + lb.z + sres * vv.z) * gv.z;
    z.w = ((xo.w - mu) * rstd * lg.w + lb.w + sres * vv.w) * gv.w;
    *(float4*)(g_z + base) = z;
}

// ---------------------------------------------------------------------------
// Host launcher
// ---------------------------------------------------------------------------
static float *P_r, *P_k, *P_vraw;
static float *P_hw, *P_ha, *P_hv, *P_hg;
static float *P_dec, *P_a, *P_v, *P_g;
static float *P_z;
static bool s_init = false;

extern "C" void kernel_launch(void* const* d_in, const int* in_sizes, int n_in,
                              void* d_out, int out_size)
{
    const float* x       = (const float*)d_in[0];
    const float* v_first = (const float*)d_in[1];
    const float* x_r = (const float*)d_in[2];
    const float* x_w = (const float*)d_in[3];
    const float* x_k = (const float*)d_in[4];
    const float* x_v = (const float*)d_in[5];
    const float* x_a = (const float*)d_in[6];
    const float* x_g = (const float*)d_in[7];
    const float* w0  = (const float*)d_in[8];
    const float* w1  = (const float*)d_in[9];
    const float* w2  = (const float*)d_in[10];
    const float* a0  = (const float*)d_in[11];
    const float* a1  = (const float*)d_in[12];
    const float* a2  = (const float*)d_in[13];
    const float* v0  = (const float*)d_in[14];
    const float* v1  = (const float*)d_in[15];
    const float* v2  = (const float*)d_in[16];
    const float* g1  = (const float*)d_in[17];
    const float* g2  = (const float*)d_in[18];
    const float* k_k = (const float*)d_in[19];
    const float* k_a = (const float*)d_in[20];
    const float* r_k = (const float*)d_in[21];
    const float* gate_w = (const float*)d_in[22];
    const float* ln_g = (const float*)d_in[23];
    const float* ln_b = (const float*)d_in[24];
    const float* Wr = (const float*)d_in[25];
    const float* Wk = (const float*)d_in[26];
    const float* Wv = (const float*)d_in[27];
    const float* Wo = (const float*)d_in[28];
    float* out = (float*)d_out;

    if (!s_init) {
        cudaGetSymbolAddress((void**)&P_r, g_r);       P_r   += SPAD;
        cudaGetSymbolAddress((void**)&P_k, g_k);
        cudaGetSymbolAddress((void**)&P_vraw, g_vraw);
        cudaGetSymbolAddress((void**)&P_hw, g_hw);
        cudaGetSymbolAddress((void**)&P_ha, g_ha);
        cudaGetSymbolAddress((void**)&P_hv, g_hv);
        cudaGetSymbolAddress((void**)&P_hg, g_hg);
        cudaGetSymbolAddress((void**)&P_dec, g_dec);   P_dec += SPAD;
        cudaGetSymbolAddress((void**)&P_a, g_a);
        cudaGetSymbolAddress((void**)&P_v, g_v);       P_v   += SPAD;
        cudaGetSymbolAddress((void**)&P_g, g_g);
        cudaGetSymbolAddress((void**)&P_z, g_z);
        s_init = true;
    }

    // 1) per-head gate
    gate_kernel<<<BT, 128>>>(x, gate_w);

    // 2) QKV — tf32 with fused mixing
    {
        QkvJobs J;
        J.A[0] = x; J.W[0] = Wr; J.C[0] = P_r;    J.mix[0] = x_r;
        J.A[1] = x; J.W[1] = Wk; J.C[1] = P_k;    J.mix[1] = x_k;
        J.A[2] = x; J.W[2] = Wv; J.C[2] = P_vraw; J.mix[2] = x_v;
        gemm_tf32_nt<<<dim3(8, 32, 3), 256>>>(J);
    }

    // 3a) stage-1 w-chain (fp32, tanh)
    {
        GemmJobs J = {};
        J.count = 1;
        J.tileStart[0] = 0; J.tileStart[1] = 1; J.tileStart[2] = 1; J.tileStart[3] = 1; J.tileStart[4] = 1;
        J.A[0] = x; J.Bm[0] = w1; J.Cm[0] = P_hw; J.N[0] = 64; J.K[0] = 512;
        J.transb[0] = 0; J.act[0] = 1; J.bias[0] = nullptr;
        J.aux1[0] = nullptr; J.aux2[0] = nullptr; J.mix[0] = x_w;
        gemm_multi<<<dim3(1, 32), 256>>>(J);
    }

    // 3b) stage-1 a/v/g hidden — tf32
    {
        Tf32Jobs J = {};
        J.count = 3;
        J.tileStart[0] = 0; J.tileStart[1] = 1; J.tileStart[2] = 2; J.tileStart[3] = 4;
        J.A[0] = x; J.Bm[0] = a1; J.Cm[0] = P_ha; J.N[0] = 64;  J.K[0] = 512; J.act[0] = 0; J.mix[0] = x_a;
        J.A[1] = x; J.Bm[1] = v1; J.Cm[1] = P_hv; J.N[1] = 32;  J.K[1] = 512; J.act[1] = 0; J.mix[1] = nullptr;
        J.A[2] = x; J.Bm[2] = g1; J.Cm[2] = P_hg; J.N[2] = 128; J.K[2] = 512; J.act[2] = 2; J.mix[2] = nullptr;
        J.mix[2] = x_g;
        for (int jj = 0; jj < 3; jj++) { J.bias[jj] = nullptr; J.aux1[jj] = nullptr; J.aux2[jj] = nullptr; }
        gemm_tf32_multi<<<dim3(4, 32), 256>>>(J);
    }

    // 4a) stage-2 a/v/g — tf32 with fused epilogues
    {
        Tf32Jobs J = {};
        J.count = 3;
        J.tileStart[0] = 0; J.tileStart[1] = 8; J.tileStart[2] = 16; J.tileStart[3] = 24;
        J.A[0] = P_ha; J.Bm[0] = a2; J.Cm[0] = P_a; J.N[0] = 512; J.K[0] = 64;  J.act[0] = 2;
        J.bias[0] = a0; J.aux1[0] = nullptr; J.aux2[0] = nullptr; J.mix[0] = nullptr;
        J.A[1] = P_hv; J.Bm[1] = v2; J.Cm[1] = P_v; J.N[1] = 512; J.K[1] = 32;  J.act[1] = 4;
        J.bias[1] = v0; J.aux1[1] = P_vraw; J.aux2[1] = v_first; J.mix[1] = nullptr;
        J.A[2] = P_hg; J.Bm[2] = g2; J.Cm[2] = P_g; J.N[2] = 512; J.K[2] = 128; J.act[2] = 0;
        J.bias[2] = nullptr; J.aux1[2] = nullptr; J.aux2[2] = nullptr; J.mix[2] = nullptr;
        gemm_tf32_multi<<<dim3(24, 32), 256>>>(J);
    }

    // 4b) stage-2 decay (fp32)
    {
        GemmJobs J = {};
        J.count = 1;
        J.tileStart[0] = 0; J.tileStart[1] = 8; J.tileStart[2] = 8; J.tileStart[3] = 8; J.tileStart[4] = 8;
        J.A[0] = P_hw; J.Bm[0] = w2; J.Cm[0] = P_dec; J.N[0] = 512; J.K[0] = 64;
        J.transb[0] = 0; J.act[0] = 3; J.bias[0] = w0;
        J.aux1[0] = nullptr; J.aux2[0] = nullptr; J.mix[0] = nullptr;
        gemm_multi<<<dim3(8, 32), 256>>>(J);
    }

    // 5) kk normalize, k', aa, bb
    post_kernel<<<BT, 128>>>(k_k, k_a);

    // 5b) A' streams + (beta,kappa) scalars
    prep2_kernel<<<BT, 128>>>();

    // 6) bidirectional WKV7 scan
    scan_kernel<<<256, 128>>>();

    // 7) combine + groupnorm + residual + *g
    combine_kernel<<<BT, 128>>>(r_k, ln_g, ln_b);

    // 8) out = z @ Wo^T — tf32
    {
        QkvJobs J;
        J.A[0] = P_z; J.W[0] = Wo; J.C[0] = out; J.mix[0] = nullptr;
        J.A[1] = P_z; J.W[1] = Wo; J.C[1] = out; J.mix[1] = nullptr;
        J.A[2] = P_z; J.W[2] = Wo; J.C[2] = out; J.mix[2] = nullptr;
        gemm_tf32_nt<<<dim3(8, 32, 1), 256>>>(J);
    }

    // 9) v_first passthrough if the flattened output includes it
    if (out_size >= 2 * BTC) {
        cudaMemcpyAsync(out + BTC, v_first, (size_t)BTC * sizeof(float),
                        cudaMemcpyDeviceToDevice, 0);
    }
}

// round 16
// speedup vs baseline: 1.0000x; 1.0000x over previous
#include <cuda_runtime.h>
#include <cstdint>
#include <math.h>

// Problem sizes (fixed)
#define BB   4
#define TT   1024
#define CC   512
#define HH   8
#define NN   64
#define BT   (BB*TT)
#define BTC  (BT*CC)
#define SPAD (10*CC)
#define BKPAD (16*HH)

typedef unsigned long long u64;

__device__ float g_gate[BT*HH];
__device__ float g_k[BTC], g_vraw[BTC];
__device__ float g_hw[BT*64], g_ha[BT*64], g_hv[BT*32], g_hg[BT*128];
__device__ float g_a[BTC], g_g[BTC];
__device__ float g_r[BTC+2*SPAD], g_dec[BTC+2*SPAD], g_v[BTC+2*SPAD];
__device__ float g_kp[BTC+2*SPAD], g_aa[BTC+2*SPAD], g_bb[BTC+2*SPAD];
__device__ float g_af[BTC+2*SPAD], g_ab[BTC+2*SPAD];
__device__ float2 g_bkf[BT*HH + 2*BKPAD], g_bkb[BT*HH + 2*BKPAD];
__device__ float g_yf[BTC+2*SPAD], g_yb[BTC+2*SPAD];
__device__ float g_z[BTC];

__device__ __forceinline__ u64 fma2(u64 a, u64 b, u64 c) {
    u64 d; asm("fma.rn.f32x2 %0, %1, %2, %3;" : "=l"(d) : "l"(a), "l"(b), "l"(c));
    return d;
}
__device__ __forceinline__ u64 mul2(u64 a, u64 b) {
    u64 d; asm("mul.rn.f32x2 %0, %1, %2;" : "=l"(d) : "l"(a), "l"(b));
    return d;
}
__device__ __forceinline__ u64 pack2(float x) {
    u64 d; uint32_t r = __float_as_uint(x);
    asm("mov.b64 %0, {%1, %1};" : "=l"(d) : "r"(r));
    return d;
}
__device__ __forceinline__ float sum2(u64 a) {
    uint32_t lo, hi;
    asm("mov.b64 {%0, %1}, %2;" : "=r"(lo), "=r"(hi) : "l"(a));
    return __uint_as_float(lo) + __uint_as_float(hi);
}

// ---------------------------------------------------------------------------
// gate kernel
// ---------------------------------------------------------------------------
__global__ void gate_kernel(const float* __restrict__ x,
                            const float* __restrict__ gate_w)
{
    int bt = blockIdx.x;
    int t  = bt & (TT - 1);
    int tid = threadIdx.x;
    int c  = tid * 4;
    size_t base = (size_t)bt * CC + c;

    float4 xc = *(const float4*)(x + base);
    float4 xp = make_float4(0.f, 0.f, 0.f, 0.f);
    if (t != 0) xp = *(const float4*)(x + base - CC);

    float4 gw = *(const float4*)(gate_w + c);
    float p = (xp.x - xc.x)*gw.x + (xp.y - xc.y)*gw.y
            + (xp.z - xc.z)*gw.z + (xp.w - xc.w)*gw.w;
    #pragma unroll
    for (int o = 1; o < 16; o <<= 1) p += __shfl_xor_sync(0xffffffffu, p, o);
    if ((tid & 15) == 0)
        g_gate[bt*HH + (tid >> 4)] = 1.f / (1.f + expf(-p));
}

__device__ __forceinline__ float4 load_mixed(const float* __restrict__ A,
                                             const float* __restrict__ mix,
                                             int row, int kc, int K)
{
    const float* ap = A + (size_t)row * K + kc;
    float4 xc = *(const float4*)ap;
    if (mix == nullptr) return xc;
    float4 xp = make_float4(0.f, 0.f, 0.f, 0.f);
    if (row & (TT - 1)) xp = *(const float4*)(ap - CC);
    float4 mx = *(const float4*)(mix + kc);
    float4 o;
    o.x = xc.x + (xp.x - xc.x) * mx.x;
    o.y = xc.y + (xp.y - xc.y) * mx.y;
    o.z = xc.z + (xp.z - xc.z) * mx.z;
    o.w = xc.w + (xp.w - xc.w) * mx.w;
    return o;
}

__device__ __forceinline__ uint32_t f2tf32(float x) {
    uint32_t r;
    asm("cvt.rna.tf32.f32 %0, %1;" : "=r"(r) : "f"(x));
    return r;
}

__device__ __forceinline__ void mma_tf32(float* d, const uint32_t* a, const uint32_t* b) {
    asm("mma.sync.aligned.m16n8k8.row.col.f32.tf32.tf32.f32 "
        "{%0,%1,%2,%3},{%4,%5,%6,%7},{%8,%9},{%0,%1,%2,%3};"
        : "+f"(d[0]), "+f"(d[1]), "+f"(d[2]), "+f"(d[3])
        : "r"(a[0]), "r"(a[1]), "r"(a[2]), "r"(a[3]), "r"(b[0]), "r"(b[1]));
}

// ---------------------------------------------------------------------------
// tf32 GEMM (B transposed, [N,K]): QKV + Wo
// ---------------------------------------------------------------------------
struct QkvJobs {
    const float* A[3];
    const float* W[3];
    float*       C[3];
    const float* mix[3];
};

__global__ __launch_bounds__(256, 2) void gemm_tf32_nt(QkvJobs J)
{
    const int K = 512, N = 512;
    const float* A = J.A[blockIdx.z];
    const float* W = J.W[blockIdx.z];
    float*       C = J.C[blockIdx.z];
    const float* mix = J.mix[blockIdx.z];

    int m0 = blockIdx.y * 128;
    int n0 = blockIdx.x * 64;

    __shared__ uint32_t As[32][136];
    __shared__ uint32_t Bs[32][72];

    int tid  = threadIdx.x;
    int warp = tid >> 5, lane = tid & 31;
    int g = lane >> 2, c = lane & 3;
    int wm = warp & 3, wn = warp >> 2;

    float acc[2][4][4];
    #pragma unroll
    for (int mt = 0; mt < 2; mt++)
        #pragma unroll
        for (int nt = 0; nt < 4; nt++)
            #pragma unroll
            for (int r = 0; r < 4; r++) acc[mt][nt][r] = 0.f;

    for (int k0 = 0; k0 < K; k0 += 32) {
        #pragma unroll
        for (int it = 0; it < 4; it++) {
            int idx = tid + it * 256;
            int m = idx >> 3, kc = (idx & 7) * 4;
            float4 v = load_mixed(A, mix, m0 + m, k0 + kc, K);
            As[kc+0][m] = f2tf32(v.x);
            As[kc+1][m] = f2tf32(v.y);
            As[kc+2][m] = f2tf32(v.z);
            As[kc+3][m] = f2tf32(v.w);
        }
        #pragma unroll
        for (int it = 0; it < 2; it++) {
            int idx = tid + it * 256;
            int n = idx >> 3, kc = (idx & 7) * 4;
            float4 v = *(const float4*)(W + (size_t)(n0 + n) * K + k0 + kc);
            Bs[kc+0][n] = f2tf32(v.x);
            Bs[kc+1][n] = f2tf32(v.y);
            Bs[kc+2][n] = f2tf32(v.z);
            Bs[kc+3][n] = f2tf32(v.w);
        }
        __syncthreads();

        #pragma unroll
        for (int k8 = 0; k8 < 4; k8++) {
            int kr = k8 * 8;
            uint32_t a[2][4], b[4][2];
            #pragma unroll
            for (int mt = 0; mt < 2; mt++) {
                int mb = wm * 32 + mt * 16;
                a[mt][0] = As[kr + c    ][mb + g    ];
                a[mt][1] = As[kr + c    ][mb + g + 8];
                a[mt][2] = As[kr + c + 4][mb + g    ];
                a[mt][3] = As[kr + c + 4][mb + g + 8];
            }
            #pragma unroll
            for (int nt = 0; nt < 4; nt++) {
                int nb = wn * 32 + nt * 8;
                b[nt][0] = Bs[kr + c    ][nb + g];
                b[nt][1] = Bs[kr + c + 4][nb + g];
            }
            #pragma unroll
            for (int mt = 0; mt < 2; mt++)
                #pragma unroll
                for (int nt = 0; nt < 4; nt++)
                    mma_tf32(acc[mt][nt], a[mt], b[nt]);
        }
        __syncthreads();
    }

    #pragma unroll
    for (int mt = 0; mt < 2; mt++) {
        int row = m0 + wm * 32 + mt * 16 + g;
        #pragma unroll
        for (int nt = 0; nt < 4; nt++) {
            int col = n0 + wn * 32 + nt * 8 + 2 * c;
            float2 v0 = make_float2(acc[mt][nt][0], acc[mt][nt][1]);
            float2 v1 = make_float2(acc[mt][nt][2], acc[mt][nt][3]);
            *(float2*)(C + (size_t)row * N + col)       = v0;
            *(float2*)(C + (size_t)(row + 8) * N + col) = v1;
        }
    }
}

// ---------------------------------------------------------------------------
// Mixed-precision multi-job GEMM (fp32 FFMA or tf32 mma per job)
// ---------------------------------------------------------------------------
struct MixJobs {
    int count;
    int tileStart[5];
    const float* A[4];
    const float* Bm[4];   // [K, N]
    float*       Cm[4];
    int N[4];
    int K[4];
    int fp32f[4];
    int act[4];
    const float* bias[4];
    const float* aux1[4];
    const float* aux2[4];
    const float* mix[4];
};

__device__ __forceinline__ float epi_apply(int act, float v, int col, size_t idx,
                                           const float* bias, const float* aux1,
                                           const float* aux2)
{
    if (act == 0) return v;
    if (act == 1) return tanhf(v);
    if (act == 2) {
        float z = v + (bias ? bias[col] : 0.f);
        return 1.f / (1.f + expf(-z));
    }
    if (act == 3) {
        float z = v + bias[col];
        float s = 1.f / (1.f + expf(-z));
        return expf(-0.60653065971263342f * s);
    }
    float z = v + bias[col];
    float s = 1.f / (1.f + expf(-z));
    float vr = aux1[idx];
    return vr + (aux2[idx] - vr) * s;
}

__global__ __launch_bounds__(256, 2) void gemm_mix(MixJobs J)
{
    int bx = blockIdx.x;
    int j = 0;
    while (bx >= J.tileStart[j + 1]) ++j;
    int n0 = (bx - J.tileStart[j]) * 64;
    int m0 = blockIdx.y * 128;

    const float* A = J.A[j];
    const float* B = J.Bm[j];
    float*       C = J.Cm[j];
    const int N = J.N[j];
    const int K = J.K[j];
    const int isf32 = J.fp32f[j];
    const float* mix = J.mix[j];

    __shared__ uint32_t As[32][136];
    __shared__ uint32_t Bs[32][72];

    int tid  = threadIdx.x;
    int warp = tid >> 5, lane = tid & 31;
    int g = lane >> 2, c = lane & 3;
    int wm = warp & 3, wn = warp >> 2;
    int tx = tid & 15, ty = tid >> 4;

    const int act = J.act[j];
    const float* bias = J.bias[j];
    const float* aux1 = J.aux1[j];
    const float* aux2 = J.aux2[j];

    if (!isf32) {
        // tf32 mma path
        float acc[2][4][4];
        #pragma unroll
        for (int mt = 0; mt < 2; mt++)
            #pragma unroll
            for (int nt = 0; nt < 4; nt++)
                #pragma unroll
                for (int r = 0; r < 4; r++) acc[mt][nt][r] = 0.f;

        for (int k0 = 0; k0 < K; k0 += 32) {
            #pragma unroll
            for (int it = 0; it < 4; it++) {
                int idx = tid + it * 256;
                int m = idx >> 3, kc = (idx & 7) * 4;
                float4 v = load_mixed(A, mix, m0 + m, k0 + kc, K);
                As[kc+0][m] = f2tf32(v.x);
                As[kc+1][m] = f2tf32(v.y);
                As[kc+2][m] = f2tf32(v.z);
                As[kc+3][m] = f2tf32(v.w);
            }
            #pragma unroll
            for (int it = 0; it < 2; it++) {
                int idx = tid + it * 256;
                int kr = idx >> 4;
                int c4 = (idx & 15) * 4;
                float4 v = make_float4(0.f, 0.f, 0.f, 0.f);
                if (n0 + c4 < N)
                    v = *(const float4*)(B + (size_t)(k0 + kr) * N + n0 + c4);
                Bs[kr][c4+0] = f2tf32(v.x);
                Bs[kr][c4+1] = f2tf32(v.y);
                Bs[kr][c4+2] = f2tf32(v.z);
                Bs[kr][c4+3] = f2tf32(v.w);
            }
            __syncthreads();

            #pragma unroll
            for (int k8 = 0; k8 < 4; k8++) {
                int kr = k8 * 8;
                uint32_t a[2][4], b[4][2];
                #pragma unroll
                for (int mt = 0; mt < 2; mt++) {
                    int mb = wm * 32 + mt * 16;
                    a[mt][0] = As[kr + c    ][mb + g    ];
                    a[mt][1] = As[kr + c    ][mb + g + 8];
                    a[mt][2] = As[kr + c + 4][mb + g    ];
                    a[mt][3] = As[kr + c + 4][mb + g + 8];
                }
                #pragma unroll
                for (int nt = 0; nt < 4; nt++) {
                    int nb = wn * 32 + nt * 8;
                    b[nt][0] = Bs[kr + c    ][nb + g];
                    b[nt][1] = Bs[kr + c + 4][nb + g];
                }
                #pragma unroll
                for (int mt = 0; mt < 2; mt++)
                    #pragma unroll
                    for (int nt = 0; nt < 4; nt++)
                        mma_tf32(acc[mt][nt], a[mt], b[nt]);
            }
            __syncthreads();
        }

        #pragma unroll
        for (int mt = 0; mt < 2; mt++) {
            int row = m0 + wm * 32 + mt * 16 + g;
            #pragma unroll
            for (int nt = 0; nt < 4; nt++) {
                int col = n0 + wn * 32 + nt * 8 + 2 * c;
                #pragma unroll
                for (int rr = 0; rr < 2; rr++) {
                    int r2 = row + rr * 8;
                    #pragma unroll
                    for (int cc = 0; cc < 2; cc++) {
                        int c2 = col + cc;
                        if (c2 < N) {
                            size_t idx = (size_t)r2 * N + c2;
                            C[idx] = epi_apply(act, acc[mt][nt][rr*2+cc], c2, idx,
                                               bias, aux1, aux2);
                        }
                    }
                }
            }
        }
    } else {
        // fp32 FFMA path (w-chain)
        float acc[8][4];
        #pragma unroll
        for (int im = 0; im < 8; im++)
            #pragma unroll
            for (int in = 0; in < 4; in++) acc[im][in] = 0.f;

        for (int k0 = 0; k0 < K; k0 += 32) {
            #pragma unroll
            for (int it = 0; it < 4; it++) {
                int idx = tid + it * 256;
                int m = idx >> 3, kc = (idx & 7) * 4;
                float4 v = load_mixed(A, mix, m0 + m, k0 + kc, K);
                As[kc+0][m] = __float_as_uint(v.x);
                As[kc+1][m] = __float_as_uint(v.y);
                As[kc+2][m] = __float_as_uint(v.z);
                As[kc+3][m] = __float_as_uint(v.w);
            }
            #pragma unroll
            for (int it = 0; it < 2; it++) {
                int idx = tid + it * 256;
                int kr = idx >> 4;
                int c4 = (idx & 15) * 4;
                float4 v = make_float4(0.f, 0.f, 0.f, 0.f);
                if (n0 + c4 < N)
                    v = *(const float4*)(B + (size_t)(k0 + kr) * N + n0 + c4);
                Bs[kr][c4+0] = __float_as_uint(v.x);
                Bs[kr][c4+1] = __float_as_uint(v.y);
                Bs[kr][c4+2] = __float_as_uint(v.z);
                Bs[kr][c4+3] = __float_as_uint(v.w);
            }
            __syncthreads();

            #pragma unroll
            for (int kk = 0; kk < 32; kk++) {
                float af[8], bf[4];
                #pragma unroll
                for (int im = 0; im < 8; im++)
                    af[im] = __uint_as_float(As[kk][ty * 8 + im]);
                #pragma unroll
                for (int in = 0; in < 4; in++)
                    bf[in] = __uint_as_float(Bs[kk][tx * 4 + in]);
                #pragma unroll
                for (int im = 0; im < 8; im++)
                    #pragma unroll
                    for (int in = 0; in < 4; in++)
                        acc[im][in] += af[im] * bf[in];
            }
            __syncthreads();
        }

        #pragma unroll
        for (int im = 0; im < 8; im++) {
            int row = m0 + ty * 8 + im;
            #pragma unroll
            for (int in = 0; in < 4; in++) {
                int col = n0 + tx * 4 + in;
                if (col < N) {
                    size_t idx = (size_t)row * N + col;
                    C[idx] = epi_apply(act, acc[im][in], col, idx,
                                       bias, aux1, aux2);
                }
            }
        }
    }
}

// ---------------------------------------------------------------------------
// post / prep2 / scan / combine (unchanged)
// ---------------------------------------------------------------------------
__global__ void post_kernel(const float* __restrict__ k_k, const float* __restrict__ k_a)
{
    int bt = blockIdx.x;
    int tid = threadIdx.x;
    int c = tid * 4;
    size_t base = (size_t)bt * CC + c;

    float4 kv = *(const float4*)(g_k + base);
    float4 av = *(const float4*)(g_a + base);
    float4 kkc = *(const float4*)(k_k + c);
    float4 kac = *(const float4*)(k_a + c);

    float4 kk;
    kk.x = kv.x * kkc.x; kk.y = kv.y * kkc.y; kk.z = kv.z * kkc.z; kk.w = kv.w * kkc.w;
    float ss = kk.x*kk.x + kk.y*kk.y + kk.z*kk.z + kk.w*kk.w;
    #pragma unroll
    for (int o = 1; o < 16; o <<= 1) ss += __shfl_xor_sync(0xffffffffu, ss, o);

    float nrm = sqrtf(ss);
    float inv = 1.f / fmaxf(nrm, 1e-12f);

    float4 aa, bb, kp;
    aa.x = -kk.x * inv; aa.y = -kk.y * inv; aa.z = -kk.z * inv; aa.w = -kk.w * inv;
    bb.x = kk.x * inv * av.x; bb.y = kk.y * inv * av.y;
    bb.z = kk.z * inv * av.z; bb.w = kk.w * inv * av.w;
    kp.x = kv.x * (1.f + (av.x - 1.f) * kac.x);
    kp.y = kv.y * (1.f + (av.y - 1.f) * kac.y);
    kp.z = kv.z * (1.f + (av.z - 1.f) * kac.z);
    kp.w = kv.w * (1.f + (av.w - 1.f) * kac.w);

    *(float4*)(g_aa + SPAD + base) = aa;
    *(float4*)(g_bb + SPAD + base) = bb;
    *(float4*)(g_kp + SPAD + base) = kp;
}

__global__ void prep2_kernel()
{
    int bt = blockIdx.x;
    int t  = bt & (TT - 1);
    int tid = threadIdx.x;
    int c = tid * 4;
    int h = tid >> 4;
    size_t base = SPAD + (size_t)bt * CC + c;

    float4 av = *(const float4*)(g_aa + base);
    float4 z4 = make_float4(0.f, 0.f, 0.f, 0.f);
    float4 dp = z4, bp = z4, kpv = z4, dn = z4, bn = z4, kn = z4;
    if (t != 0) {
        dp  = *(const float4*)(g_dec + base - CC);
        bp  = *(const float4*)(g_bb  + base - CC);
        kpv = *(const float4*)(g_kp  + base - CC);
    }
    if (t != TT - 1) {
        dn = *(const float4*)(g_dec + base + CC);
        bn = *(const float4*)(g_bb  + base + CC);
        kn = *(const float4*)(g_kp  + base + CC);
    }

    float4 af, ab;
    af.x = dp.x*av.x; af.y = dp.y*av.y; af.z = dp.z*av.z; af.w = dp.w*av.w;
    ab.x = dn.x*av.x; ab.y = dn.y*av.y; ab.z = dn.z*av.z; ab.w = dn.w*av.w;
    *(float4*)(g_af + base) = af;
    *(float4*)(g_ab + base) = ab;

    float bf_ = bp.x*av.x + bp.y*av.y + bp.z*av.z + bp.w*av.w;
    float kf_ = kpv.x*av.x + kpv.y*av.y + kpv.z*av.z + kpv.w*av.w;
    float bb_ = bn.x*av.x + bn.y*av.y + bn.z*av.z + bn.w*av.w;
    float kb_ = kn.x*av.x + kn.y*av.y + kn.z*av.z + kn.w*av.w;
    #pragma unroll
    for (int o = 1; o < 16; o <<= 1) {
        bf_ += __shfl_xor_sync(0xffffffffu, bf_, o);
        kf_ += __shfl_xor_sync(0xffffffffu, kf_, o);
        bb_ += __shfl_xor_sync(0xffffffffu, bb_, o);
        kb_ += __shfl_xor_sync(0xffffffffu, kb_, o);
    }
    if ((tid & 15) == 0) {
        g_bkf[BKPAD + bt*HH + h] = make_float2(bf_, kf_);
        g_bkb[BKPAD + bt*HH + h] = make_float2(bb_, kb_);
    }
}

template<int CS>
__device__ __forceinline__ void scan_step(
    int tstep,
    u64& S0a, u64& S1a, u64& S0b, u64& S1b,
    u64 (&R)[4][2], u64 (&D)[4][2], u64 (&K)[4][2],
    u64 (&B)[4][2], u64 (&A2)[4][2],
    float (&V0)[4], float (&V1)[4], float2 (&BK)[4],
    float (&zf0)[2], float (&zf1)[2], float (&yf0)[2], float (&yf1)[2],
    float& sa_prev0, float& sa_prev1, float& vprev0, float& vprev1,
    const float*& pr4, const float*& pd4, const float*& pk4,
    const float*& pb4, const float*& pA6,
    const float*& pv04, const float*& pv14, const float2*& pbk4,
    float* py0, float* py1, int stride, int sbk, int q)
{
    constexpr int P = CS & 1;

    float2 bk = BK[CS];
    float sa0 = fmaf(vprev0, bk.y, fmaf(sa_prev0, bk.x, zf0[P]));
    float sa1 = fmaf(vprev1, bk.y, fmaf(sa_prev1, bk.x, zf1[P]));

    if (q == 0 && (unsigned)(tstep - 2) < (unsigned)TT) {
        *py0 = yf0[P]; *py1 = yf1[P];
    }

    u64 sa20 = pack2(sa0), sa21 = pack2(sa1);
    float v0s = V0[CS], v1s = V1[CS];
    u64 v20 = pack2(v0s), v21 = pack2(v1s);
    S0a = fma2(S0a, D[CS][0], fma2(sa20, B[CS][0], mul2(v20, K[CS][0])));
    S1a = fma2(S1a, D[CS][1], fma2(sa20, B[CS][1], mul2(v20, K[CS][1])));
    S0b = fma2(S0b, D[CS][0], fma2(sa21, B[CS][0], mul2(v21, K[CS][0])));
    S1b = fma2(S1b, D[CS][1], fma2(sa21, B[CS][1], mul2(v21, K[CS][1])));

    float ya = sum2(fma2(S1a, R[CS][1],  mul2(S0a, R[CS][0])));
    float za = sum2(fma2(S1a, A2[CS][1], mul2(S0a, A2[CS][0])));
    float yb = sum2(fma2(S1b, R[CS][1],  mul2(S0b, R[CS][0])));
    float zb = sum2(fma2(S1b, A2[CS][1], mul2(S0b, A2[CS][0])));

    sa_prev0 = sa0; sa_prev1 = sa1; vprev0 = v0s; vprev1 = v1s;

    {
        ulonglong2 rv = *(const ulonglong2*)pr4;
        ulonglong2 dv = *(const ulonglong2*)pd4;
        ulonglong2 kv = *(const ulonglong2*)pk4;
        ulonglong2 bv = *(const ulonglong2*)pb4;
        ulonglong2 av = *(const ulonglong2*)pA6;
        R[CS][0]  = rv.x; R[CS][1]  = rv.y;
        D[CS][0]  = dv.x; D[CS][1]  = dv.y;
        K[CS][0]  = kv.x; K[CS][1]  = kv.y;
        B[CS][0]  = bv.x; B[CS][1]  = bv.y;
        A2[CS][0] = av.x; A2[CS][1] = av.y;
        V0[CS] = *pv04;
        V1[CS] = *pv14;
        BK[CS] = *pbk4;
    }
    pr4 += stride; pd4 += stride; pk4 += stride; pb4 += stride;
    pA6 += stride; pv04 += stride; pv14 += stride; pbk4 += sbk;

    #pragma unroll
    for (int o = 1; o < 16; o <<= 1) {
        ya += __shfl_xor_sync(0xffffffffu, ya, o);
        za += __shfl_xor_sync(0xffffffffu, za, o);
        yb += __shfl_xor_sync(0xffffffffu, yb, o);
        zb += __shfl_xor_sync(0xffffffffu, zb, o);
    }
    yf0[P] = ya; zf0[P] = za; yf1[P] = yb; zf1[P] = zb;
}

__global__ __launch_bounds__(128, 2) void scan_kernel()
{
    int bx = blockIdx.x;
    int dir = bx >> 7;
    int b   = (bx >> 5) & 3;
    int h   = (bx >> 2) & 7;
    int rg  = bx & 3;
    int tid = threadIdx.x;
    int rp  = tid >> 4;
    int q   = tid & 15;
    int c0  = q * 4;
    int i0  = rg * 16 + rp;
    int i1  = i0 + 8;

    int t0 = dir ? (TT - 1) : 0;
    int stride = dir ? -CC : CC;
    int sbk = dir ? -HH : HH;
    size_t off = SPAD + (size_t)(b * TT + t0) * CC + h * NN;

    const float* pr = g_r   + off + c0;
    const float* pd = g_dec + off + c0;
    const float* pk = g_kp  + off + c0;
    const float* pb = g_bb  + off + c0;
    const float* pA = (dir ? g_ab : g_af) + off + c0;
    const float* pv0 = g_v + off + i0;
    const float* pv1 = g_v + off + i1;
    const float2* pbk = (dir ? g_bkb : g_bkf) + BKPAD + (size_t)(b * TT + t0) * HH + h;

    float* ybase = (dir ? g_yb : g_yf);
    float* py0 = ybase + off + i0 - 2*stride;
    float* py1 = ybase + off + i1 - 2*stride;

    u64 S0a = 0, S1a = 0, S0b = 0, S1b = 0;
    u64 R[4][2], D[4][2], K[4][2], B[4][2], A2[4][2];
    float V0[4], V1[4];
    float2 BK[4];

    #pragma unroll
    for (int s = 0; s < 4; s++) {
        ulonglong2 v;
        v = *(const ulonglong2*)(pr + s*stride);     R[s][0]=v.x;  R[s][1]=v.y;
        v = *(const ulonglong2*)(pd + s*stride);     D[s][0]=v.x;  D[s][1]=v.y;
        v = *(const ulonglong2*)(pk + s*stride);     K[s][0]=v.x;  K[s][1]=v.y;
        v = *(const ulonglong2*)(pb + s*stride);     B[s][0]=v.x;  B[s][1]=v.y;
        v = *(const ulonglong2*)(pA + (s+2)*stride); A2[s][0]=v.x; A2[s][1]=v.y;
        V0[s] = *(pv0 + s*stride);
        V1[s] = *(pv1 + s*stride);
        BK[s] = *(pbk + s*sbk);
    }

    const float* pr4  = pr + 4*stride;
    const float* pd4  = pd + 4*stride;
    const float* pk4  = pk + 4*stride;
    const float* pb4  = pb + 4*stride;
    const float* pA6  = pA + 6*stride;
    const float* pv04 = pv0 + 4*stride;
    const float* pv14 = pv1 + 4*stride;
    const float2* pbk4 = pbk + 4*sbk;

    float zf0[2] = {0.f, 0.f}, zf1[2] = {0.f, 0.f};
    float yf0[2] = {0.f, 0.f}, yf1[2] = {0.f, 0.f};
    float sa_prev0 = 0.f, sa_prev1 = 0.f, vprev0 = 0.f, vprev1 = 0.f;

    for (int t = 0; t < TT + 4; t += 4) {
        scan_step<0>(t+0, S0a,S1a,S0b,S1b, R,D,K,B,A2, V0,V1,BK, zf0,zf1,yf0,yf1,
                     sa_prev0,sa_prev1,vprev0,vprev1,
                     pr4,pd4,pk4,pb4,pA6,pv04,pv14,pbk4, py0,py1, stride,sbk,q);
        py0 += stride; py1 += stride;
        scan_step<1>(t+1, S0a,S1a,S0b,S1b, R,D,K,B,A2, V0,V1,BK, zf0,zf1,yf0,yf1,
                     sa_prev0,sa_prev1,vprev0,vprev1,
                     pr4,pd4,pk4,pb4,pA6,pv04,pv14,pbk4, py0,py1, stride,sbk,q);
        py0 += stride; py1 += stride;
        scan_step<2>(t+2, S0a,S1a,S0b,S1b, R,D,K,B,A2, V0,V1,BK, zf0,zf1,yf0,yf1,
                     sa_prev0,sa_prev1,vprev0,vprev1,
                     pr4,pd4,pk4,pb4,pA6,pv04,pv14,pbk4, py0,py1, stride,sbk,q);
        py0 += stride; py1 += stride;
        scan_step<3>(t+3, S0a,S1a,S0b,S1b, R,D,K,B,A2, V0,V1,BK, zf0,zf1,yf0,yf1,
                     sa_prev0,sa_prev1,vprev0,vprev1,
                     pr4,pd4,pk4,pb4,pA6,pv04,pv14,pbk4, py0,py1, stride,sbk,q);
        py0 += stride; py1 += stride;
    }
}

__global__ void combine_kernel(const float* __restrict__ r_k,
                               const float* __restrict__ ln_g,
                               const float* __restrict__ ln_b)
{
    int bt = blockIdx.x;
    int tid = threadIdx.x;
    int c = tid * 4;
    int h = tid >> 4;
    size_t base = (size_t)bt * CC + c;

    float4 yf = *(const float4*)(g_yf + SPAD + base);
    float4 yb = *(const float4*)(g_yb + SPAD + base);
    float gate = g_gate[bt * HH + h];

    float4 xo;
    xo.x = gate * yf.x + (1.f - gate) * yb.x;
    xo.y = gate * yf.y + (1.f - gate) * yb.y;
    xo.z = gate * yf.z + (1.f - gate) * yb.z;
    xo.w = gate * yf.w + (1.f - gate) * yb.w;

    float4 rv = *(const float4*)(g_r + SPAD + base);
    float4 kp = *(const float4*)(g_kp + SPAD + base);
    float4 vv = *(const float4*)(g_v + SPAD + base);
    float4 gv = *(const float4*)(g_g + base);
    float4 rk = *(const float4*)(r_k + c);

    float sum = xo.x + xo.y + xo.z + xo.w;
    float sq  = xo.x*xo.x + xo.y*xo.y + xo.z*xo.z + xo.w*xo.w;
    float sres = rv.x*kp.x*rk.x + rv.y*kp.y*rk.y + rv.z*kp.z*rk.z + rv.w*kp.w*rk.w;
    #pragma unroll
    for (int o = 1; o < 16; o <<= 1) {
        sum  += __shfl_xor_sync(0xffffffffu, sum, o);
        sq   += __shfl_xor_sync(0xffffffffu, sq, o);
        sres += __shfl_xor_sync(0xffffffffu, sres, o);
    }
    float mu = sum * (1.f / 64.f);
    float var = sq * (1.f / 64.f) - mu * mu;
    float rstd = rsqrtf(var + 0.00064f);

    float4 lg = *(const float4*)(ln_g + c);
    float4 lb = *(const float4*)(ln_b + c);

    float4 z;
    z.x = ((xo.x - mu) * rstd * lg.x + lb.x + sres * vv.x) * gv.x;
    z.y = ((xo.y - mu) * rstd * lg.y + lb.y + sres * vv.y) * gv.y;
    z.z = ((xo.z - mu) * rstd * lg.z + lb.z + sres * vv.z) * gv.z;
    z.w = ((xo.w - mu) * rstd * lg.w + lb.w + sres * vv.w) * gv.w;
    *(float4*)(g_z + base) = z;
}

// ---------------------------------------------------------------------------
// Host launcher
// ---------------------------------------------------------------------------
static float *P_r, *P_k, *P_vraw;
static float *P_hw, *P_ha, *P_hv, *P_hg;
static float *P_dec, *P_a, *P_v, *P_g;
static float *P_z;
static bool s_init = false;

extern "C" void kernel_launch(void* const* d_in, const int* in_sizes, int n_in,
                              void* d_out, int out_size)
{
    const float* x       = (const float*)d_in[0];
    const float* v_first = (const float*)d_in[1];
    const float* x_r = (const float*)d_in[2];
    const float* x_w = (const float*)d_in[3];
    const float* x_k = (const float*)d_in[4];
    const float* x_v = (const float*)d_in[5];
    const float* x_a = (const float*)d_in[6];
    const float* x_g = (const float*)d_in[7];
    const float* w0  = (const float*)d_in[8];
    const float* w1  = (const float*)d_in[9];
    const float* w2  = (const float*)d_in[10];
    const float* a0  = (const float*)d_in[11];
    const float* a1  = (const float*)d_in[12];
    const float* a2  = (const float*)d_in[13];
    const float* v0  = (const float*)d_in[14];
    const float* v1  = (const float*)d_in[15];
    const float* v2  = (const float*)d_in[16];
    const float* g1  = (const float*)d_in[17];
    const float* g2  = (const float*)d_in[18];
    const float* k_k = (const float*)d_in[19];
    const float* k_a = (const float*)d_in[20];
    const float* r_k = (const float*)d_in[21];
    const float* gate_w = (const float*)d_in[22];
    const float* ln_g = (const float*)d_in[23];
    const float* ln_b = (const float*)d_in[24];
    const float* Wr = (const float*)d_in[25];
    const float* Wk = (const float*)d_in[26];
    const float* Wv = (const float*)d_in[27];
    const float* Wo = (const float*)d_in[28];
    float* out = (float*)d_out;

    if (!s_init) {
        cudaGetSymbolAddress((void**)&P_r, g_r);       P_r   += SPAD;
        cudaGetSymbolAddress((void**)&P_k, g_k);
        cudaGetSymbolAddress((void**)&P_vraw, g_vraw);
        cudaGetSymbolAddress((void**)&P_hw, g_hw);
        cudaGetSymbolAddress((void**)&P_ha, g_ha);
        cudaGetSymbolAddress((void**)&P_hv, g_hv);
        cudaGetSymbolAddress((void**)&P_hg, g_hg);
        cudaGetSymbolAddress((void**)&P_dec, g_dec);   P_dec += SPAD;
        cudaGetSymbolAddress((void**)&P_a, g_a);
        cudaGetSymbolAddress((void**)&P_v, g_v);       P_v   += SPAD;
        cudaGetSymbolAddress((void**)&P_g, g_g);
        cudaGetSymbolAddress((void**)&P_z, g_z);
        s_init = true;
    }

    // 1) per-head gate
    gate_kernel<<<BT, 128>>>(x, gate_w);

    // 2) QKV — tf32 with fused mixing
    {
        QkvJobs J;
        J.A[0] = x; J.W[0] = Wr; J.C[0] = P_r;    J.mix[0] = x_r;
        J.A[1] = x; J.W[1] = Wk; J.C[1] = P_k;    J.mix[1] = x_k;
        J.A[2] = x; J.W[2] = Wv; J.C[2] = P_vraw; J.mix[2] = x_v;
        gemm_tf32_nt<<<dim3(8, 32, 3), 256>>>(J);
    }

    // 3) stage-1 — ONE launch: w (fp32 tanh) + a/v/g (tf32)
    {
        MixJobs J = {};
        J.count = 4;
        J.tileStart[0] = 0; J.tileStart[1] = 1; J.tileStart[2] = 2;
        J.tileStart[3] = 3; J.tileStart[4] = 5;
        J.A[0] = x; J.Bm[0] = w1; J.Cm[0] = P_hw; J.N[0] = 64;  J.K[0] = 512;
        J.fp32f[0] = 1; J.act[0] = 1; J.mix[0] = x_w;
        J.A[1] = x; J.Bm[1] = a1; J.Cm[1] = P_ha; J.N[1] = 64;  J.K[1] = 512;
        J.fp32f[1] = 0; J.act[1] = 0; J.mix[1] = x_a;
        J.A[2] = x; J.Bm[2] = v1; J.Cm[2] = P_hv; J.N[2] = 32;  J.K[2] = 512;
        J.fp32f[2] = 0; J.act[2] = 0; J.mix[2] = nullptr;
        J.A[3] = x; J.Bm[3] = g1; J.Cm[3] = P_hg; J.N[3] = 128; J.K[3] = 512;
        J.fp32f[3] = 0; J.act[3] = 2; J.mix[3] = x_g;
        for (int jj = 0; jj < 4; jj++) { J.bias[jj] = nullptr; J.aux1[jj] = nullptr; J.aux2[jj] = nullptr; }
        gemm_mix<<<dim3(5, 32), 256>>>(J);
    }

    // 4) stage-2 — ONE launch: dec (fp32) + a/v/g (tf32), fused epilogues
    {
        MixJobs J = {};
        J.count = 4;
        J.tileStart[0] = 0; J.tileStart[1] = 8; J.tileStart[2] = 16;
        J.tileStart[3] = 24; J.tileStart[4] = 32;
        J.A[0] = P_hw; J.Bm[0] = w2; J.Cm[0] = P_dec; J.N[0] = 512; J.K[0] = 64;
        J.fp32f[0] = 1; J.act[0] = 3; J.bias[0] = w0;
        J.aux1[0] = nullptr; J.aux2[0] = nullptr; J.mix[0] = nullptr;
        J.A[1] = P_ha; J.Bm[1] = a2; J.Cm[1] = P_a; J.N[1] = 512; J.K[1] = 64;
        J.fp32f[1] = 0; J.act[1] = 2; J.bias[1] = a0;
        J.aux1[1] = nullptr; J.aux2[1] = nullptr; J.mix[1] = nullptr;
        J.A[2] = P_hv; J.Bm[2] = v2; J.Cm[2] = P_v; J.N[2] = 512; J.K[2] = 32;
        J.fp32f[2] = 0; J.act[2] = 4; J.bias[2] = v0;
        J.aux1[2] = P_vraw; J.aux2[2] = v_first; J.mix[2] = nullptr;
        J.A[3] = P_hg; J.Bm[3] = g2; J.Cm[3] = P_g; J.N[3] = 512; J.K[3] = 128;
        J.fp32f[3] = 0; J.act[3] = 0; J.bias[3] = nullptr;
        J.aux1[3] = nullptr; J.aux2[3] = nullptr; J.mix[3] = nullptr;
        gemm_mix<<<dim3(32, 32), 256>>>(J);
    }

    // 5) kk normalize, k', aa, bb
    post_kernel<<<BT, 128>>>(k_k, k_a);

    // 5b) A' streams + (beta,kappa) scalars
    prep2_kernel<<<BT, 128>>>();

    // 6) bidirectional WKV7 scan
    scan_kernel<<<256, 128>>>();

    // 7) combine + groupnorm + residual + *g
    combine_kernel<<<BT, 128>>>(r_k, ln_g, ln_b);

    // 8) out = z @ Wo^T — tf32
    {
        QkvJobs J;
        J.A[0] = P_z; J.W[0] = Wo; J.C[0] = out; J.mix[0] = nullptr;
        J.A[1] = P_z; J.W[1] = Wo; J.C[1] = out; J.mix[1] = nullptr;
        J.A[2] = P_z; J.W[2] = Wo; J.C[2] = out; J.mix[2] = nullptr;
        gemm_tf32_nt<<<dim3(8, 32, 1), 256>>>(J);
    }

    // 9) v_first passthrough if the flattened output includes it
    if (out_size >= 2 * BTC) {
        cudaMemcpyAsync(out + BTC, v_first, (size_t)BTC * sizeof(float),
                        cudaMemcpyDeviceToDevice, 0);
    }
}

// round 17
// speedup vs baseline: 1.0470x; 1.0470x over previous
#include <cuda_runtime.h>
#include <cstdint>
#include <math.h>

// Problem sizes (fixed)
#define BB   4
#define TT   1024
#define CC   512
#define HH   8
#define NN   64
#define BT   (BB*TT)
#define BTC  (BT*CC)
#define SPAD (10*CC)
#define BKPAD (16*HH)

typedef unsigned long long u64;

__device__ float g_gate[BT*HH];
__device__ float g_k[BTC], g_vraw[BTC];
__device__ float g_hw[BT*64], g_ha[BT*64], g_hv[BT*32], g_hg[BT*128];
__device__ float g_a[BTC], g_g[BTC];
__device__ float g_r[BTC+2*SPAD], g_dec[BTC+2*SPAD], g_v[BTC+2*SPAD];
__device__ float g_kp[BTC+2*SPAD], g_aa[BTC+2*SPAD], g_bb[BTC+2*SPAD];
__device__ float g_af[BTC+2*SPAD], g_ab[BTC+2*SPAD];
__device__ float2 g_bkf[BT*HH + 2*BKPAD], g_bkb[BT*HH + 2*BKPAD];
__device__ float g_yf[BTC+2*SPAD], g_yb[BTC+2*SPAD];
__device__ float g_z[BTC];

__device__ __forceinline__ u64 fma2(u64 a, u64 b, u64 c) {
    u64 d; asm("fma.rn.f32x2 %0, %1, %2, %3;" : "=l"(d) : "l"(a), "l"(b), "l"(c));
    return d;
}
__device__ __forceinline__ u64 mul2(u64 a, u64 b) {
    u64 d; asm("mul.rn.f32x2 %0, %1, %2;" : "=l"(d) : "l"(a), "l"(b));
    return d;
}
__device__ __forceinline__ u64 pack2(float x) {
    u64 d; uint32_t r = __float_as_uint(x);
    asm("mov.b64 %0, {%1, %1};" : "=l"(d) : "r"(r));
    return d;
}
__device__ __forceinline__ float sum2(u64 a) {
    uint32_t lo, hi;
    asm("mov.b64 {%0, %1}, %2;" : "=r"(lo), "=r"(hi) : "l"(a));
    return __uint_as_float(lo) + __uint_as_float(hi);
}

// ---------------------------------------------------------------------------
// gate kernel
// ---------------------------------------------------------------------------
__global__ void gate_kernel(const float* __restrict__ x,
                            const float* __restrict__ gate_w)
{
    int bt = blockIdx.x;
    int t  = bt & (TT - 1);
    int tid = threadIdx.x;
    int c  = tid * 4;
    size_t base = (size_t)bt * CC + c;

    float4 xc = *(const float4*)(x + base);
    float4 xp = make_float4(0.f, 0.f, 0.f, 0.f);
    if (t != 0) xp = *(const float4*)(x + base - CC);

    float4 gw = *(const float4*)(gate_w + c);
    float p = (xp.x - xc.x)*gw.x + (xp.y - xc.y)*gw.y
            + (xp.z - xc.z)*gw.z + (xp.w - xc.w)*gw.w;
    #pragma unroll
    for (int o = 1; o < 16; o <<= 1) p += __shfl_xor_sync(0xffffffffu, p, o);
    if ((tid & 15) == 0)
        g_gate[bt*HH + (tid >> 4)] = 1.f / (1.f + expf(-p));
}

__device__ __forceinline__ float4 load_mixed(const float* __restrict__ A,
                                             const float* __restrict__ mix,
                                             int row, int kc, int K)
{
    const float* ap = A + (size_t)row * K + kc;
    float4 xc = *(const float4*)ap;
    if (mix == nullptr) return xc;
    float4 xp = make_float4(0.f, 0.f, 0.f, 0.f);
    if (row & (TT - 1)) xp = *(const float4*)(ap - CC);
    float4 mx = *(const float4*)(mix + kc);
    float4 o;
    o.x = xc.x + (xp.x - xc.x) * mx.x;
    o.y = xc.y + (xp.y - xc.y) * mx.y;
    o.z = xc.z + (xp.z - xc.z) * mx.z;
    o.w = xc.w + (xp.w - xc.w) * mx.w;
    return o;
}

__device__ __forceinline__ uint32_t f2tf32(float x) {
    uint32_t r;
    asm("cvt.rna.tf32.f32 %0, %1;" : "=r"(r) : "f"(x));
    return r;
}

__device__ __forceinline__ void mma_tf32(float* d, const uint32_t* a, const uint32_t* b) {
    asm("mma.sync.aligned.m16n8k8.row.col.f32.tf32.tf32.f32 "
        "{%0,%1,%2,%3},{%4,%5,%6,%7},{%8,%9},{%0,%1,%2,%3};"
        : "+f"(d[0]), "+f"(d[1]), "+f"(d[2]), "+f"(d[3])
        : "r"(a[0]), "r"(a[1]), "r"(a[2]), "r"(a[3]), "r"(b[0]), "r"(b[1]));
}

// ---------------------------------------------------------------------------
// tf32 GEMM (B transposed, [N,K]): QKV + Wo
// ---------------------------------------------------------------------------
struct QkvJobs {
    const float* A[3];
    const float* W[3];
    float*       C[3];
    const float* mix[3];
};

__global__ __launch_bounds__(256, 2) void gemm_tf32_nt(QkvJobs J)
{
    const int K = 512, N = 512;
    const float* A = J.A[blockIdx.z];
    const float* W = J.W[blockIdx.z];
    float*       C = J.C[blockIdx.z];
    const float* mix = J.mix[blockIdx.z];

    int m0 = blockIdx.y * 128;
    int n0 = blockIdx.x * 64;

    __shared__ uint32_t As[32][136];
    __shared__ uint32_t Bs[32][72];

    int tid  = threadIdx.x;
    int warp = tid >> 5, lane = tid & 31;
    int g = lane >> 2, c = lane & 3;
    int wm = warp & 3, wn = warp >> 2;

    float acc[2][4][4];
    #pragma unroll
    for (int mt = 0; mt < 2; mt++)
        #pragma unroll
        for (int nt = 0; nt < 4; nt++)
            #pragma unroll
            for (int r = 0; r < 4; r++) acc[mt][nt][r] = 0.f;

    for (int k0 = 0; k0 < K; k0 += 32) {
        #pragma unroll
        for (int it = 0; it < 4; it++) {
            int idx = tid + it * 256;
            int m = idx >> 3, kc = (idx & 7) * 4;
            float4 v = load_mixed(A, mix, m0 + m, k0 + kc, K);
            As[kc+0][m] = f2tf32(v.x);
            As[kc+1][m] = f2tf32(v.y);
            As[kc+2][m] = f2tf32(v.z);
            As[kc+3][m] = f2tf32(v.w);
        }
        #pragma unroll
        for (int it = 0; it < 2; it++) {
            int idx = tid + it * 256;
            int n = idx >> 3, kc = (idx & 7) * 4;
            float4 v = *(const float4*)(W + (size_t)(n0 + n) * K + k0 + kc);
            Bs[kc+0][n] = f2tf32(v.x);
            Bs[kc+1][n] = f2tf32(v.y);
            Bs[kc+2][n] = f2tf32(v.z);
            Bs[kc+3][n] = f2tf32(v.w);
        }
        __syncthreads();

        #pragma unroll
        for (int k8 = 0; k8 < 4; k8++) {
            int kr = k8 * 8;
            uint32_t a[2][4], b[4][2];
            #pragma unroll
            for (int mt = 0; mt < 2; mt++) {
                int mb = wm * 32 + mt * 16;
                a[mt][0] = As[kr + c    ][mb + g    ];
                a[mt][1] = As[kr + c    ][mb + g + 8];
                a[mt][2] = As[kr + c + 4][mb + g    ];
                a[mt][3] = As[kr + c + 4][mb + g + 8];
            }
            #pragma unroll
            for (int nt = 0; nt < 4; nt++) {
                int nb = wn * 32 + nt * 8;
                b[nt][0] = Bs[kr + c    ][nb + g];
                b[nt][1] = Bs[kr + c + 4][nb + g];
            }
            #pragma unroll
            for (int mt = 0; mt < 2; mt++)
                #pragma unroll
                for (int nt = 0; nt < 4; nt++)
                    mma_tf32(acc[mt][nt], a[mt], b[nt]);
        }
        __syncthreads();
    }

    #pragma unroll
    for (int mt = 0; mt < 2; mt++) {
        int row = m0 + wm * 32 + mt * 16 + g;
        #pragma unroll
        for (int nt = 0; nt < 4; nt++) {
            int col = n0 + wn * 32 + nt * 8 + 2 * c;
            float2 v0 = make_float2(acc[mt][nt][0], acc[mt][nt][1]);
            float2 v1 = make_float2(acc[mt][nt][2], acc[mt][nt][3]);
            *(float2*)(C + (size_t)row * N + col)       = v0;
            *(float2*)(C + (size_t)(row + 8) * N + col) = v1;
        }
    }
}

// ---------------------------------------------------------------------------
// Mixed-precision multi-job GEMM (fp32 FFMA or tf32 mma per job)
// ---------------------------------------------------------------------------
struct MixJobs {
    int count;
    int tileStart[5];
    const float* A[4];
    const float* Bm[4];   // [K, N]
    float*       Cm[4];
    int N[4];
    int K[4];
    int fp32f[4];
    int act[4];
    const float* bias[4];
    const float* aux1[4];
    const float* aux2[4];
    const float* mix[4];
};

__device__ __forceinline__ float epi_apply(int act, float v, int col, size_t idx,
                                           const float* bias, const float* aux1,
                                           const float* aux2)
{
    if (act == 0) return v;
    if (act == 1) return tanhf(v);
    if (act == 2) {
        float z = v + (bias ? bias[col] : 0.f);
        return 1.f / (1.f + expf(-z));
    }
    if (act == 3) {
        float z = v + bias[col];
        float s = 1.f / (1.f + expf(-z));
        return expf(-0.60653065971263342f * s);
    }
    float z = v + bias[col];
    float s = 1.f / (1.f + expf(-z));
    float vr = aux1[idx];
    return vr + (aux2[idx] - vr) * s;
}

__global__ __launch_bounds__(256, 2) void gemm_mix(MixJobs J)
{
    int bx = blockIdx.x;
    int j = 0;
    while (bx >= J.tileStart[j + 1]) ++j;
    int n0 = (bx - J.tileStart[j]) * 64;
    int m0 = blockIdx.y * 128;

    const float* A = J.A[j];
    const float* B = J.Bm[j];
    float*       C = J.Cm[j];
    const int N = J.N[j];
    const int K = J.K[j];
    const int isf32 = J.fp32f[j];
    const float* mix = J.mix[j];

    __shared__ uint32_t As[32][136];
    __shared__ uint32_t Bs[32][72];

    int tid  = threadIdx.x;
    int warp = tid >> 5, lane = tid & 31;
    int g = lane >> 2, c = lane & 3;
    int wm = warp & 3, wn = warp >> 2;
    int tx = tid & 15, ty = tid >> 4;

    const int act = J.act[j];
    const float* bias = J.bias[j];
    const float* aux1 = J.aux1[j];
    const float* aux2 = J.aux2[j];

    if (!isf32) {
        float acc[2][4][4];
        #pragma unroll
        for (int mt = 0; mt < 2; mt++)
            #pragma unroll
            for (int nt = 0; nt < 4; nt++)
                #pragma unroll
                for (int r = 0; r < 4; r++) acc[mt][nt][r] = 0.f;

        for (int k0 = 0; k0 < K; k0 += 32) {
            #pragma unroll
            for (int it = 0; it < 4; it++) {
                int idx = tid + it * 256;
                int m = idx >> 3, kc = (idx & 7) * 4;
                float4 v = load_mixed(A, mix, m0 + m, k0 + kc, K);
                As[kc+0][m] = f2tf32(v.x);
                As[kc+1][m] = f2tf32(v.y);
                As[kc+2][m] = f2tf32(v.z);
                As[kc+3][m] = f2tf32(v.w);
            }
            #pragma unroll
            for (int it = 0; it < 2; it++) {
                int idx = tid + it * 256;
                int kr = idx >> 4;
                int c4 = (idx & 15) * 4;
                float4 v = make_float4(0.f, 0.f, 0.f, 0.f);
                if (n0 + c4 < N)
                    v = *(const float4*)(B + (size_t)(k0 + kr) * N + n0 + c4);
                Bs[kr][c4+0] = f2tf32(v.x);
                Bs[kr][c4+1] = f2tf32(v.y);
                Bs[kr][c4+2] = f2tf32(v.z);
                Bs[kr][c4+3] = f2tf32(v.w);
            }
            __syncthreads();

            #pragma unroll
            for (int k8 = 0; k8 < 4; k8++) {
                int kr = k8 * 8;
                uint32_t a[2][4], b[4][2];
                #pragma unroll
                for (int mt = 0; mt < 2; mt++) {
                    int mb = wm * 32 + mt * 16;
                    a[mt][0] = As[kr + c    ][mb + g    ];
                    a[mt][1] = As[kr + c    ][mb + g + 8];
                    a[mt][2] = As[kr + c + 4][mb + g    ];
                    a[mt][3] = As[kr + c + 4][mb + g + 8];
                }
                #pragma unroll
                for (int nt = 0; nt < 4; nt++) {
                    int nb = wn * 32 + nt * 8;
                    b[nt][0] = Bs[kr + c    ][nb + g];
                    b[nt][1] = Bs[kr + c + 4][nb + g];
                }
                #pragma unroll
                for (int mt = 0; mt < 2; mt++)
                    #pragma unroll
                    for (int nt = 0; nt < 4; nt++)
                        mma_tf32(acc[mt][nt], a[mt], b[nt]);
            }
            __syncthreads();
        }

        #pragma unroll
        for (int mt = 0; mt < 2; mt++) {
            int row = m0 + wm * 32 + mt * 16 + g;
            #pragma unroll
            for (int nt = 0; nt < 4; nt++) {
                int col = n0 + wn * 32 + nt * 8 + 2 * c;
                #pragma unroll
                for (int rr = 0; rr < 2; rr++) {
                    int r2 = row + rr * 8;
                    #pragma unroll
                    for (int cc = 0; cc < 2; cc++) {
                        int c2 = col + cc;
                        if (c2 < N) {
                            size_t idx = (size_t)r2 * N + c2;
                            C[idx] = epi_apply(act, acc[mt][nt][rr*2+cc], c2, idx,
                                               bias, aux1, aux2);
                        }
                    }
                }
            }
        }
    } else {
        float acc[8][4];
        #pragma unroll
        for (int im = 0; im < 8; im++)
            #pragma unroll
            for (int in = 0; in < 4; in++) acc[im][in] = 0.f;

        for (int k0 = 0; k0 < K; k0 += 32) {
            #pragma unroll
            for (int it = 0; it < 4; it++) {
                int idx = tid + it * 256;
                int m = idx >> 3, kc = (idx & 7) * 4;
                float4 v = load_mixed(A, mix, m0 + m, k0 + kc, K);
                As[kc+0][m] = __float_as_uint(v.x);
                As[kc+1][m] = __float_as_uint(v.y);
                As[kc+2][m] = __float_as_uint(v.z);
                As[kc+3][m] = __float_as_uint(v.w);
            }
            #pragma unroll
            for (int it = 0; it < 2; it++) {
                int idx = tid + it * 256;
                int kr = idx >> 4;
                int c4 = (idx & 15) * 4;
                float4 v = make_float4(0.f, 0.f, 0.f, 0.f);
                if (n0 + c4 < N)
                    v = *(const float4*)(B + (size_t)(k0 + kr) * N + n0 + c4);
                Bs[kr][c4+0] = __float_as_uint(v.x);
                Bs[kr][c4+1] = __float_as_uint(v.y);
                Bs[kr][c4+2] = __float_as_uint(v.z);
                Bs[kr][c4+3] = __float_as_uint(v.w);
            }
            __syncthreads();

            #pragma unroll
            for (int kk = 0; kk < 32; kk++) {
                float af[8], bf[4];
                #pragma unroll
                for (int im = 0; im < 8; im++)
                    af[im] = __uint_as_float(As[kk][ty * 8 + im]);
                #pragma unroll
                for (int in = 0; in < 4; in++)
                    bf[in] = __uint_as_float(Bs[kk][tx * 4 + in]);
                #pragma unroll
                for (int im = 0; im < 8; im++)
                    #pragma unroll
                    for (int in = 0; in < 4; in++)
                        acc[im][in] += af[im] * bf[in];
            }
            __syncthreads();
        }

        #pragma unroll
        for (int im = 0; im < 8; im++) {
            int row = m0 + ty * 8 + im;
            #pragma unroll
            for (int in = 0; in < 4; in++) {
                int col = n0 + tx * 4 + in;
                if (col < N) {
                    size_t idx = (size_t)row * N + col;
                    C[idx] = epi_apply(act, acc[im][in], col, idx,
                                       bias, aux1, aux2);
                }
            }
        }
    }
}

// ---------------------------------------------------------------------------
// post / prep2 / scan / combine (unchanged)
// ---------------------------------------------------------------------------
__global__ void post_kernel(const float* __restrict__ k_k, const float* __restrict__ k_a)
{
    int bt = blockIdx.x;
    int tid = threadIdx.x;
    int c = tid * 4;
    size_t base = (size_t)bt * CC + c;

    float4 kv = *(const float4*)(g_k + base);
    float4 av = *(const float4*)(g_a + base);
    float4 kkc = *(const float4*)(k_k + c);
    float4 kac = *(const float4*)(k_a + c);

    float4 kk;
    kk.x = kv.x * kkc.x; kk.y = kv.y * kkc.y; kk.z = kv.z * kkc.z; kk.w = kv.w * kkc.w;
    float ss = kk.x*kk.x + kk.y*kk.y + kk.z*kk.z + kk.w*kk.w;
    #pragma unroll
    for (int o = 1; o < 16; o <<= 1) ss += __shfl_xor_sync(0xffffffffu, ss, o);

    float nrm = sqrtf(ss);
    float inv = 1.f / fmaxf(nrm, 1e-12f);

    float4 aa, bb, kp;
    aa.x = -kk.x * inv; aa.y = -kk.y * inv; aa.z = -kk.z * inv; aa.w = -kk.w * inv;
    bb.x = kk.x * inv * av.x; bb.y = kk.y * inv * av.y;
    bb.z = kk.z * inv * av.z; bb.w = kk.w * inv * av.w;
    kp.x = kv.x * (1.f + (av.x - 1.f) * kac.x);
    kp.y = kv.y * (1.f + (av.y - 1.f) * kac.y);
    kp.z = kv.z * (1.f + (av.z - 1.f) * kac.z);
    kp.w = kv.w * (1.f + (av.w - 1.f) * kac.w);

    *(float4*)(g_aa + SPAD + base) = aa;
    *(float4*)(g_bb + SPAD + base) = bb;
    *(float4*)(g_kp + SPAD + base) = kp;
}

__global__ void prep2_kernel()
{
    int bt = blockIdx.x;
    int t  = bt & (TT - 1);
    int tid = threadIdx.x;
    int c = tid * 4;
    int h = tid >> 4;
    size_t base = SPAD + (size_t)bt * CC + c;

    float4 av = *(const float4*)(g_aa + base);
    float4 z4 = make_float4(0.f, 0.f, 0.f, 0.f);
    float4 dp = z4, bp = z4, kpv = z4, dn = z4, bn = z4, kn = z4;
    if (t != 0) {
        dp  = *(const float4*)(g_dec + base - CC);
        bp  = *(const float4*)(g_bb  + base - CC);
        kpv = *(const float4*)(g_kp  + base - CC);
    }
    if (t != TT - 1) {
        dn = *(const float4*)(g_dec + base + CC);
        bn = *(const float4*)(g_bb  + base + CC);
        kn = *(const float4*)(g_kp  + base + CC);
    }

    float4 af, ab;
    af.x = dp.x*av.x; af.y = dp.y*av.y; af.z = dp.z*av.z; af.w = dp.w*av.w;
    ab.x = dn.x*av.x; ab.y = dn.y*av.y; ab.z = dn.z*av.z; ab.w = dn.w*av.w;
    *(float4*)(g_af + base) = af;
    *(float4*)(g_ab + base) = ab;

    float bf_ = bp.x*av.x + bp.y*av.y + bp.z*av.z + bp.w*av.w;
    float kf_ = kpv.x*av.x + kpv.y*av.y + kpv.z*av.z + kpv.w*av.w;
    float bb_ = bn.x*av.x + bn.y*av.y + bn.z*av.z + bn.w*av.w;
    float kb_ = kn.x*av.x + kn.y*av.y + kn.z*av.z + kn.w*av.w;
    #pragma unroll
    for (int o = 1; o < 16; o <<= 1) {
        bf_ += __shfl_xor_sync(0xffffffffu, bf_, o);
        kf_ += __shfl_xor_sync(0xffffffffu, kf_, o);
        bb_ += __shfl_xor_sync(0xffffffffu, bb_, o);
        kb_ += __shfl_xor_sync(0xffffffffu, kb_, o);
    }
    if ((tid & 15) == 0) {
        g_bkf[BKPAD + bt*HH + h] = make_float2(bf_, kf_);
        g_bkb[BKPAD + bt*HH + h] = make_float2(bb_, kb_);
    }
}

template<int CS>
__device__ __forceinline__ void scan_step(
    int tstep,
    u64& S0a, u64& S1a, u64& S0b, u64& S1b,
    u64 (&R)[4][2], u64 (&D)[4][2], u64 (&K)[4][2],
    u64 (&B)[4][2], u64 (&A2)[4][2],
    float (&V0)[4], float (&V1)[4], float2 (&BK)[4],
    float (&zf0)[2], float (&zf1)[2], float (&yf0)[2], float (&yf1)[2],
    float& sa_prev0, float& sa_prev1, float& vprev0, float& vprev1,
    const float*& pr4, const float*& pd4, const float*& pk4,
    const float*& pb4, const float*& pA6,
    const float*& pv04, const float*& pv14, const float2*& pbk4,
    float* py0, float* py1, int stride, int sbk, int q)
{
    constexpr int P = CS & 1;

    float2 bk = BK[CS];
    float sa0 = fmaf(vprev0, bk.y, fmaf(sa_prev0, bk.x, zf0[P]));
    float sa1 = fmaf(vprev1, bk.y, fmaf(sa_prev1, bk.x, zf1[P]));

    if (q == 0 && (unsigned)(tstep - 2) < (unsigned)TT) {
        *py0 = yf0[P]; *py1 = yf1[P];
    }

    u64 sa20 = pack2(sa0), sa21 = pack2(sa1);
    float v0s = V0[CS], v1s = V1[CS];
    u64 v20 = pack2(v0s), v21 = pack2(v1s);
    S0a = fma2(S0a, D[CS][0], fma2(sa20, B[CS][0], mul2(v20, K[CS][0])));
    S1a = fma2(S1a, D[CS][1], fma2(sa20, B[CS][1], mul2(v20, K[CS][1])));
    S0b = fma2(S0b, D[CS][0], fma2(sa21, B[CS][0], mul2(v21, K[CS][0])));
    S1b = fma2(S1b, D[CS][1], fma2(sa21, B[CS][1], mul2(v21, K[CS][1])));

    float ya = sum2(fma2(S1a, R[CS][1],  mul2(S0a, R[CS][0])));
    float za = sum2(fma2(S1a, A2[CS][1], mul2(S0a, A2[CS][0])));
    float yb = sum2(fma2(S1b, R[CS][1],  mul2(S0b, R[CS][0])));
    float zb = sum2(fma2(S1b, A2[CS][1], mul2(S0b, A2[CS][0])));

    sa_prev0 = sa0; sa_prev1 = sa1; vprev0 = v0s; vprev1 = v1s;

    {
        ulonglong2 rv = *(const ulonglong2*)pr4;
        ulonglong2 dv = *(const ulonglong2*)pd4;
        ulonglong2 kv = *(const ulonglong2*)pk4;
        ulonglong2 bv = *(const ulonglong2*)pb4;
        ulonglong2 av = *(const ulonglong2*)pA6;
        R[CS][0]  = rv.x; R[CS][1]  = rv.y;
        D[CS][0]  = dv.x; D[CS][1]  = dv.y;
        K[CS][0]  = kv.x; K[CS][1]  = kv.y;
        B[CS][0]  = bv.x; B[CS][1]  = bv.y;
        A2[CS][0] = av.x; A2[CS][1] = av.y;
        V0[CS] = *pv04;
        V1[CS] = *pv14;
        BK[CS] = *pbk4;
    }
    pr4 += stride; pd4 += stride; pk4 += stride; pb4 += stride;
    pA6 += stride; pv04 += stride; pv14 += stride; pbk4 += sbk;

    #pragma unroll
    for (int o = 1; o < 16; o <<= 1) {
        ya += __shfl_xor_sync(0xffffffffu, ya, o);
        za += __shfl_xor_sync(0xffffffffu, za, o);
        yb += __shfl_xor_sync(0xffffffffu, yb, o);
        zb += __shfl_xor_sync(0xffffffffu, zb, o);
    }
    yf0[P] = ya; zf0[P] = za; yf1[P] = yb; zf1[P] = zb;
}

__global__ __launch_bounds__(128, 2) void scan_kernel()
{
    int bx = blockIdx.x;
    int dir = bx >> 7;
    int b   = (bx >> 5) & 3;
    int h   = (bx >> 2) & 7;
    int rg  = bx & 3;
    int tid = threadIdx.x;
    int rp  = tid >> 4;
    int q   = tid & 15;
    int c0  = q * 4;
    int i0  = rg * 16 + rp;
    int i1  = i0 + 8;

    int t0 = dir ? (TT - 1) : 0;
    int stride = dir ? -CC : CC;
    int sbk = dir ? -HH : HH;
    size_t off = SPAD + (size_t)(b * TT + t0) * CC + h * NN;

    const float* pr = g_r   + off + c0;
    const float* pd = g_dec + off + c0;
    const float* pk = g_kp  + off + c0;
    const float* pb = g_bb  + off + c0;
    const float* pA = (dir ? g_ab : g_af) + off + c0;
    const float* pv0 = g_v + off + i0;
    const float* pv1 = g_v + off + i1;
    const float2* pbk = (dir ? g_bkb : g_bkf) + BKPAD + (size_t)(b * TT + t0) * HH + h;

    float* ybase = (dir ? g_yb : g_yf);
    float* py0 = ybase + off + i0 - 2*stride;
    float* py1 = ybase + off + i1 - 2*stride;

    u64 S0a = 0, S1a = 0, S0b = 0, S1b = 0;
    u64 R[4][2], D[4][2], K[4][2], B[4][2], A2[4][2];
    float V0[4], V1[4];
    float2 BK[4];

    #pragma unroll
    for (int s = 0; s < 4; s++) {
        ulonglong2 v;
        v = *(const ulonglong2*)(pr + s*stride);     R[s][0]=v.x;  R[s][1]=v.y;
        v = *(const ulonglong2*)(pd + s*stride);     D[s][0]=v.x;  D[s][1]=v.y;
        v = *(const ulonglong2*)(pk + s*stride);     K[s][0]=v.x;  K[s][1]=v.y;
        v = *(const ulonglong2*)(pb + s*stride);     B[s][0]=v.x;  B[s][1]=v.y;
        v = *(const ulonglong2*)(pA + (s+2)*stride); A2[s][0]=v.x; A2[s][1]=v.y;
        V0[s] = *(pv0 + s*stride);
        V1[s] = *(pv1 + s*stride);
        BK[s] = *(pbk + s*sbk);
    }

    const float* pr4  = pr + 4*stride;
    const float* pd4  = pd + 4*stride;
    const float* pk4  = pk + 4*stride;
    const float* pb4  = pb + 4*stride;
    const float* pA6  = pA + 6*stride;
    const float* pv04 = pv0 + 4*stride;
    const float* pv14 = pv1 + 4*stride;
    const float2* pbk4 = pbk + 4*sbk;

    float zf0[2] = {0.f, 0.f}, zf1[2] = {0.f, 0.f};
    float yf0[2] = {0.f, 0.f}, yf1[2] = {0.f, 0.f};
    float sa_prev0 = 0.f, sa_prev1 = 0.f, vprev0 = 0.f, vprev1 = 0.f;

    for (int t = 0; t < TT + 4; t += 4) {
        scan_step<0>(t+0, S0a,S1a,S0b,S1b, R,D,K,B,A2, V0,V1,BK, zf0,zf1,yf0,yf1,
                     sa_prev0,sa_prev1,vprev0,vprev1,
                     pr4,pd4,pk4,pb4,pA6,pv04,pv14,pbk4, py0,py1, stride,sbk,q);
        py0 += stride; py1 += stride;
        scan_step<1>(t+1, S0a,S1a,S0b,S1b, R,D,K,B,A2, V0,V1,BK, zf0,zf1,yf0,yf1,
                     sa_prev0,sa_prev1,vprev0,vprev1,
                     pr4,pd4,pk4,pb4,pA6,pv04,pv14,pbk4, py0,py1, stride,sbk,q);
        py0 += stride; py1 += stride;
        scan_step<2>(t+2, S0a,S1a,S0b,S1b, R,D,K,B,A2, V0,V1,BK, zf0,zf1,yf0,yf1,
                     sa_prev0,sa_prev1,vprev0,vprev1,
                     pr4,pd4,pk4,pb4,pA6,pv04,pv14,pbk4, py0,py1, stride,sbk,q);
        py0 += stride; py1 += stride;
        scan_step<3>(t+3, S0a,S1a,S0b,S1b, R,D,K,B,A2, V0,V1,BK, zf0,zf1,yf0,yf1,
                     sa_prev0,sa_prev1,vprev0,vprev1,
                     pr4,pd4,pk4,pb4,pA6,pv04,pv14,pbk4, py0,py1, stride,sbk,q);
        py0 += stride; py1 += stride;
    }
}

__global__ void combine_kernel(const float* __restrict__ r_k,
                               const float* __restrict__ ln_g,
                               const float* __restrict__ ln_b)
{
    int bt = blockIdx.x;
    int tid = threadIdx.x;
    int c = tid * 4;
    int h = tid >> 4;
    size_t base = (size_t)bt * CC + c;

    float4 yf = *(const float4*)(g_yf + SPAD + base);
    float4 yb = *(const float4*)(g_yb + SPAD + base);
    float gate = g_gate[bt * HH + h];

    float4 xo;
    xo.x = gate * yf.x + (1.f - gate) * yb.x;
    xo.y = gate * yf.y + (1.f - gate) * yb.y;
    xo.z = gate * yf.z + (1.f - gate) * yb.z;
    xo.w = gate * yf.w + (1.f - gate) * yb.w;

    float4 rv = *(const float4*)(g_r + SPAD + base);
    float4 kp = *(const float4*)(g_kp + SPAD + base);
    float4 vv = *(const float4*)(g_v + SPAD + base);
    float4 gv = *(const float4*)(g_g + base);
    float4 rk = *(const float4*)(r_k + c);

    float sum = xo.x + xo.y + xo.z + xo.w;
    float sq  = xo.x*xo.x + xo.y*xo.y + xo.z*xo.z + xo.w*xo.w;
    float sres = rv.x*kp.x*rk.x + rv.y*kp.y*rk.y + rv.z*kp.z*rk.z + rv.w*kp.w*rk.w;
    #pragma unroll
    for (int o = 1; o < 16; o <<= 1) {
        sum  += __shfl_xor_sync(0xffffffffu, sum, o);
        sq   += __shfl_xor_sync(0xffffffffu, sq, o);
        sres += __shfl_xor_sync(0xffffffffu, sres, o);
    }
    float mu = sum * (1.f / 64.f);
    float var = sq * (1.f / 64.f) - mu * mu;
    float rstd = rsqrtf(var + 0.00064f);

    float4 lg = *(const float4*)(ln_g + c);
    float4 lb = *(const float4*)(ln_b + c);

    float4 z;
    z.x = ((xo.x - mu) * rstd * lg.x + lb.x + sres * vv.x) * gv.x;
    z.y = ((xo.y - mu) * rstd * lg.y + lb.y + sres * vv.y) * gv.y;
    z.z = ((xo.z - mu) * rstd * lg.z + lb.z + sres * vv.z) * gv.z;
    z.w = ((xo.w - mu) * rstd * lg.w + lb.w + sres * vv.w) * gv.w;
    *(float4*)(g_z + base) = z;
}

// ---------------------------------------------------------------------------
// Host launcher — fork-join stream overlap for gate/stage-1 vs QKV
// ---------------------------------------------------------------------------
static float *P_r, *P_k, *P_vraw;
static float *P_hw, *P_ha, *P_hv, *P_hg;
static float *P_dec, *P_a, *P_v, *P_g;
static float *P_z;
static cudaStream_t s_side = nullptr;
static cudaEvent_t  s_evFork = nullptr, s_evJoin = nullptr;
static bool s_init = false;

extern "C" void kernel_launch(void* const* d_in, const int* in_sizes, int n_in,
                              void* d_out, int out_size)
{
    const float* x       = (const float*)d_in[0];
    const float* v_first = (const float*)d_in[1];
    const float* x_r = (const float*)d_in[2];
    const float* x_w = (const float*)d_in[3];
    const float* x_k = (const float*)d_in[4];
    const float* x_v = (const float*)d_in[5];
    const float* x_a = (const float*)d_in[6];
    const float* x_g = (const float*)d_in[7];
    const float* w0  = (const float*)d_in[8];
    const float* w1  = (const float*)d_in[9];
    const float* w2  = (const float*)d_in[10];
    const float* a0  = (const float*)d_in[11];
    const float* a1  = (const float*)d_in[12];
    const float* a2  = (const float*)d_in[13];
    const float* v0  = (const float*)d_in[14];
    const float* v1  = (const float*)d_in[15];
    const float* v2  = (const float*)d_in[16];
    const float* g1  = (const float*)d_in[17];
    const float* g2  = (const float*)d_in[18];
    const float* k_k = (const float*)d_in[19];
    const float* k_a = (const float*)d_in[20];
    const float* r_k = (const float*)d_in[21];
    const float* gate_w = (const float*)d_in[22];
    const float* ln_g = (const float*)d_in[23];
    const float* ln_b = (const float*)d_in[24];
    const float* Wr = (const float*)d_in[25];
    const float* Wk = (const float*)d_in[26];
    const float* Wv = (const float*)d_in[27];
    const float* Wo = (const float*)d_in[28];
    float* out = (float*)d_out;

    if (!s_init) {
        cudaGetSymbolAddress((void**)&P_r, g_r);       P_r   += SPAD;
        cudaGetSymbolAddress((void**)&P_k, g_k);
        cudaGetSymbolAddress((void**)&P_vraw, g_vraw);
        cudaGetSymbolAddress((void**)&P_hw, g_hw);
        cudaGetSymbolAddress((void**)&P_ha, g_ha);
        cudaGetSymbolAddress((void**)&P_hv, g_hv);
        cudaGetSymbolAddress((void**)&P_hg, g_hg);
        cudaGetSymbolAddress((void**)&P_dec, g_dec);   P_dec += SPAD;
        cudaGetSymbolAddress((void**)&P_a, g_a);
        cudaGetSymbolAddress((void**)&P_v, g_v);       P_v   += SPAD;
        cudaGetSymbolAddress((void**)&P_g, g_g);
        cudaGetSymbolAddress((void**)&P_z, g_z);
        cudaStreamCreateWithFlags(&s_side, cudaStreamNonBlocking);
        cudaEventCreateWithFlags(&s_evFork, cudaEventDisableTiming);
        cudaEventCreateWithFlags(&s_evJoin, cudaEventDisableTiming);
        s_init = true;
    }

    // ---- fork: side stream runs gate + stage-1 concurrently with QKV ----
    cudaEventRecord(s_evFork, 0);
    cudaStreamWaitEvent(s_side, s_evFork, 0);

    // side stream: gate + stage-1
    gate_kernel<<<BT, 128, 0, s_side>>>(x, gate_w);
    {
        MixJobs J = {};
        J.count = 4;
        J.tileStart[0] = 0; J.tileStart[1] = 1; J.tileStart[2] = 2;
        J.tileStart[3] = 3; J.tileStart[4] = 5;
        J.A[0] = x; J.Bm[0] = w1; J.Cm[0] = P_hw; J.N[0] = 64;  J.K[0] = 512;
        J.fp32f[0] = 1; J.act[0] = 1; J.mix[0] = x_w;
        J.A[1] = x; J.Bm[1] = a1; J.Cm[1] = P_ha; J.N[1] = 64;  J.K[1] = 512;
        J.fp32f[1] = 0; J.act[1] = 0; J.mix[1] = x_a;
        J.A[2] = x; J.Bm[2] = v1; J.Cm[2] = P_hv; J.N[2] = 32;  J.K[2] = 512;
        J.fp32f[2] = 0; J.act[2] = 0; J.mix[2] = nullptr;
        J.A[3] = x; J.Bm[3] = g1; J.Cm[3] = P_hg; J.N[3] = 128; J.K[3] = 512;
        J.fp32f[3] = 0; J.act[3] = 2; J.mix[3] = x_g;
        for (int jj = 0; jj < 4; jj++) { J.bias[jj] = nullptr; J.aux1[jj] = nullptr; J.aux2[jj] = nullptr; }
        gemm_mix<<<dim3(5, 32), 256, 0, s_side>>>(J);
    }
    cudaEventRecord(s_evJoin, s_side);

    // default stream: QKV
    {
        QkvJobs J;
        J.A[0] = x; J.W[0] = Wr; J.C[0] = P_r;    J.mix[0] = x_r;
        J.A[1] = x; J.W[1] = Wk; J.C[1] = P_k;    J.mix[1] = x_k;
        J.A[2] = x; J.W[2] = Wv; J.C[2] = P_vraw; J.mix[2] = x_v;
        gemm_tf32_nt<<<dim3(8, 32, 3), 256>>>(J);
    }

    // ---- join: stage-2 needs stage-1 + QKV outputs ----
    cudaStreamWaitEvent(0, s_evJoin, 0);

    {
        MixJobs J = {};
        J.count = 4;
        J.tileStart[0] = 0; J.tileStart[1] = 8; J.tileStart[2] = 16;
        J.tileStart[3] = 24; J.tileStart[4] = 32;
        J.A[0] = P_hw; J.Bm[0] = w2; J.Cm[0] = P_dec; J.N[0] = 512; J.K[0] = 64;
        J.fp32f[0] = 1; J.act[0] = 3; J.bias[0] = w0;
        J.aux1[0] = nullptr; J.aux2[0] = nullptr; J.mix[0] = nullptr;
        J.A[1] = P_ha; J.Bm[1] = a2; J.Cm[1] = P_a; J.N[1] = 512; J.K[1] = 64;
        J.fp32f[1] = 0; J.act[1] = 2; J.bias[1] = a0;
        J.aux1[1] = nullptr; J.aux2[1] = nullptr; J.mix[1] = nullptr;
        J.A[2] = P_hv; J.Bm[2] = v2; J.Cm[2] = P_v; J.N[2] = 512; J.K[2] = 32;
        J.fp32f[2] = 0; J.act[2] = 4; J.bias[2] = v0;
        J.aux1[2] = P_vraw; J.aux2[2] = v_first; J.mix[2] = nullptr;
        J.A[3] = P_hg; J.Bm[3] = g2; J.Cm[3] = P_g; J.N[3] = 512; J.K[3] = 128;
        J.fp32f[3] = 0; J.act[3] = 0; J.bias[3] = nullptr;
        J.aux1[3] = nullptr; J.aux2[3] = nullptr; J.mix[3] = nullptr;
        gemm_mix<<<dim3(32, 32), 256>>>(J);
    }

    post_kernel<<<BT, 128>>>(k_k, k_a);
    prep2_kernel<<<BT, 128>>>();
    scan_kernel<<<256, 128>>>();
    combine_kernel<<<BT, 128>>>(r_k, ln_g, ln_b);

    {
        QkvJobs J;
        J.A[0] = P_z; J.W[0] = Wo; J.C[0] = out; J.mix[0] = nullptr;
        J.A[1] = P_z; J.W[1] = Wo; J.C[1] = out; J.mix[1] = nullptr;
        J.A[2] = P_z; J.W[2] = Wo; J.C[2] = out; J.mix[2] = nullptr;
        gemm_tf32_nt<<<dim3(8, 32, 1), 256>>>(J);
    }

    if (out_size >= 2 * BTC) {
        cudaMemcpyAsync(out + BTC, v_first, (size_t)BTC * sizeof(float),
                        cudaMemcpyDeviceToDevice, 0);
    }
}